// round 2
// baseline (speedup 1.0000x reference)
#include <cuda_runtime.h>
#include <cuda_bf16.h>

#define E_EDGES 1024
#define N_NODES 8192
#define ZD      256
#define KK_RANK 819

// ---- scratch (device globals: allocation-free) ----
__device__ float          g_simi[E_EDGES * N_NODES];          // 32 MB [e][n]
__device__ unsigned short g_Bh[E_EDGES * N_NODES];            // 16 MB bf16 bits: H * w_hi
__device__ unsigned short g_Bl[E_EDGES * N_NODES];            // 16 MB bf16 bits: H * w_lo
__device__ float          g_DV2[N_NODES];

// =====================================================================
// Kernel 1: simi[e][n] = dot(hyper_params[y[e/16]*16 + e%16], x[n])  (fp32)
// Tiles: 64(e) x 128(n), BK=32, 256 threads, each thread 4x8 outputs.
// =====================================================================
__global__ __launch_bounds__(256) void k_simi(
    const float* __restrict__ x, const int* __restrict__ y,
    const float* __restrict__ hp)
{
    __shared__ float As[32][65];    // [k][e]  (+1 pad)
    __shared__ float Bs[32][129];   // [k][n]  (+1 pad)
    const int be = blockIdx.y * 64;
    const int bn = blockIdx.x * 128;
    const int tid = threadIdx.x;
    const int ty = tid >> 4, tx = tid & 15;

    float acc[4][8];
    #pragma unroll
    for (int i = 0; i < 4; i++)
        #pragma unroll
        for (int j = 0; j < 8; j++) acc[i][j] = 0.f;

    for (int k0 = 0; k0 < ZD; k0 += 32) {
        #pragma unroll
        for (int p = 0; p < 2; p++) {               // A tile 64x32 (512 float4 slots)
            int idx = tid + p * 256;
            int e   = idx >> 3;
            int k4  = (idx & 7) << 2;
            int ge  = be + e;
            int row = y[ge >> 4] * 16 + (ge & 15);
            float4 v = *(const float4*)(hp + (size_t)row * ZD + k0 + k4);
            As[k4+0][e] = v.x; As[k4+1][e] = v.y; As[k4+2][e] = v.z; As[k4+3][e] = v.w;
        }
        #pragma unroll
        for (int p = 0; p < 4; p++) {               // B tile 128x32 (1024 float4 slots)
            int idx = tid + p * 256;
            int n   = idx >> 3;
            int k4  = (idx & 7) << 2;
            float4 v = *(const float4*)(x + (size_t)(bn + n) * ZD + k0 + k4);
            Bs[k4+0][n] = v.x; Bs[k4+1][n] = v.y; Bs[k4+2][n] = v.z; Bs[k4+3][n] = v.w;
        }
        __syncthreads();
        #pragma unroll
        for (int k = 0; k < 32; k++) {
            float a[4], b[8];
            #pragma unroll
            for (int mi = 0; mi < 4; mi++) a[mi] = As[k][ty + 16 * mi];
            #pragma unroll
            for (int ni = 0; ni < 8; ni++) b[ni] = Bs[k][tx + 16 * ni];
            #pragma unroll
            for (int mi = 0; mi < 4; mi++)
                #pragma unroll
                for (int ni = 0; ni < 8; ni++)
                    acc[mi][ni] = fmaf(a[mi], b[ni], acc[mi][ni]);
        }
        __syncthreads();
    }
    #pragma unroll
    for (int mi = 0; mi < 4; mi++)
        #pragma unroll
        for (int ni = 0; ni < 8; ni++)
            g_simi[(size_t)(be + ty + 16 * mi) * N_NODES + bn + tx + 16 * ni] = acc[mi][ni];
}

// =====================================================================
// Kernel 2: per-edge exact radix select (819th largest), build Bh/Bl.
// One block per edge, 256 threads, values staged in smem.
// =====================================================================
__global__ __launch_bounds__(256) void k_select()
{
    __shared__ unsigned su[N_NODES];
    __shared__ unsigned hist[256];
    __shared__ unsigned s_bin, s_r, s_above;

    const int e = blockIdx.x;
    const int t = threadIdx.x;
    const float* row = g_simi + (size_t)e * N_NODES;

    #pragma unroll 4
    for (int i = 0; i < 32; i++) {
        unsigned b = __float_as_uint(row[i * 256 + t]);
        su[i * 256 + t] = (b & 0x80000000u) ? ~b : (b | 0x80000000u);
    }
    if (t == 0) { s_r = KK_RANK; s_above = 0; }
    __syncthreads();

    unsigned prefix = 0, pmask = 0;
    for (int level = 0; level < 4; level++) {
        int shift = 24 - 8 * level;
        hist[t] = 0;
        __syncthreads();
        #pragma unroll 4
        for (int i = 0; i < 32; i++) {
            unsigned u = su[i * 256 + t];
            if ((u & pmask) == prefix) atomicAdd(&hist[(u >> shift) & 0xFFu], 1u);
        }
        __syncthreads();
        if (t == 0) {
            unsigned r = s_r, above = s_above;
            int b;
            for (b = 255; b >= 0; b--) {
                unsigned c = hist[b];
                if (c >= r) break;
                r -= c; above += c;
            }
            s_bin = (unsigned)b; s_r = r; s_above = above;
        }
        __syncthreads();
        prefix |= (s_bin << shift);
        pmask  |= (0xFFu << shift);
        __syncthreads();
    }

    const unsigned thr = prefix;          // exact bits of kk-th largest
    const unsigned de  = s_above;         // #{u > thr}  == DE
    float w = 1.0f / (float)de;
    __nv_bfloat16 whi = __float2bfloat16(w);
    __nv_bfloat16 wlo = __float2bfloat16(w - __bfloat162float(whi));
    unsigned short whiB = *(unsigned short*)&whi;
    unsigned short wloB = *(unsigned short*)&wlo;

    #pragma unroll 4
    for (int i = 0; i < 32; i++) {
        int n = i * 256 + t;
        bool g = su[n] > thr;
        g_Bh[(size_t)e * N_NODES + n] = g ? whiB : (unsigned short)0;
        g_Bl[(size_t)e * N_NODES + n] = g ? wloB : (unsigned short)0;
    }
}

// =====================================================================
// Kernel 3: DV2[n] = rsqrt( #edges containing n )
// =====================================================================
__global__ __launch_bounds__(256) void k_dv()
{
    int n = blockIdx.x * 256 + threadIdx.x;
    int cnt = 0;
    #pragma unroll 8
    for (int e = 0; e < E_EDGES; e++)
        cnt += (g_Bh[(size_t)e * N_NODES + n] != 0);
    g_DV2[n] = rsqrtf((float)cnt);
}

// =====================================================================
// Kernel 4: G = diag(DV2) * (H diag(1/DE) H^T) * diag(DV2)
// C[i,j] = sum_{k<2048} A[k,i]*B[k,j],  A = (Bh!=0)->1.0bf16 (both halves),
// B = [Bh ; Bl].  128x128x32 tiles, mma.sync m16n8k16 bf16, 8 warps (2x4).
// =====================================================================
__global__ __launch_bounds__(256) void k_gemm(float* __restrict__ G)
{
    __shared__ unsigned short As[2][128][40];   // [m][k], stride 40 -> conflict-free frags
    __shared__ unsigned short Bs[2][128][40];   // [n][k]

    const int bi = blockIdx.y, bj = blockIdx.x;
    const int i0 = bi * 128, j0 = bj * 128;
    const int tid  = threadIdx.x;
    const int lane = tid & 31, warp = tid >> 5;
    const int wm = warp >> 2, wn = warp & 3;    // 2 x 4 warp grid
    const int r = lane >> 2, q = lane & 3;

    float c[4][4][4];
    #pragma unroll
    for (int a = 0; a < 4; a++)
        #pragma unroll
        for (int b = 0; b < 4; b++)
            #pragma unroll
            for (int d = 0; d < 4; d++) c[a][b][d] = 0.f;

    ushort4 sa[4], sb[4];

    // 32(k) x 128(col) tile = 1024 four-column (8B) chunks; 256 threads x 4.
    auto LOAD = [&](int kt) {
        #pragma unroll
        for (int p = 0; p < 4; p++) {
            int pos = tid + p * 256;            // 0..1023
            int kk  = pos >> 5;                 // 0..31
            int c4  = (pos & 31) << 2;          // 0..124
            int kg  = kt * 32 + kk;
            int e   = kg & 1023;
            sa[p] = *(const ushort4*)(g_Bh + (size_t)e * N_NODES + i0 + c4);
            const unsigned short* src = (kg < 1024) ? g_Bh : g_Bl;
            sb[p] = *(const ushort4*)(src + (size_t)e * N_NODES + j0 + c4);
        }
    };
    auto STORE = [&](int buf) {
        const unsigned short ONE = 0x3F80;      // bf16 1.0
        #pragma unroll
        for (int p = 0; p < 4; p++) {
            int pos = tid + p * 256;
            int kk  = pos >> 5;
            int c4  = (pos & 31) << 2;
            unsigned short av[4] = {sa[p].x, sa[p].y, sa[p].z, sa[p].w};
            unsigned short bv[4] = {sb[p].x, sb[p].y, sb[p].z, sb[p].w};
            #pragma unroll
            for (int cc = 0; cc < 4; cc++) {
                As[buf][c4 + cc][kk] = av[cc] ? ONE : (unsigned short)0;
                Bs[buf][c4 + cc][kk] = bv[cc];
            }
        }
    };
    auto COMPUTE = [&](int buf) {
        #pragma unroll
        for (int kh = 0; kh < 2; kh++) {
            int kb = kh * 16;
            unsigned af[4][4], bf_[4][2];
            #pragma unroll
            for (int mt = 0; mt < 4; mt++) {
                int m = wm * 64 + mt * 16;
                af[mt][0] = *(const unsigned*)&As[buf][m + r    ][kb + 2*q    ];
                af[mt][1] = *(const unsigned*)&As[buf][m + r + 8][kb + 2*q    ];
                af[mt][2] = *(const unsigned*)&As[buf][m + r    ][kb + 2*q + 8];
                af[mt][3] = *(const unsigned*)&As[buf][m + r + 8][kb + 2*q + 8];
            }
            #pragma unroll
            for (int nt = 0; nt < 4; nt++) {
                int n = wn * 32 + nt * 8;
                bf_[nt][0] = *(const unsigned*)&Bs[buf][n + r][kb + 2*q    ];
                bf_[nt][1] = *(const unsigned*)&Bs[buf][n + r][kb + 2*q + 8];
            }
            #pragma unroll
            for (int mt = 0; mt < 4; mt++)
                #pragma unroll
                for (int nt = 0; nt < 4; nt++) {
                    asm volatile(
                        "mma.sync.aligned.m16n8k16.row.col.f32.bf16.bf16.f32 "
                        "{%0,%1,%2,%3},{%4,%5,%6,%7},{%8,%9},{%0,%1,%2,%3};\n"
                        : "+f"(c[mt][nt][0]), "+f"(c[mt][nt][1]),
                          "+f"(c[mt][nt][2]), "+f"(c[mt][nt][3])
                        : "r"(af[mt][0]), "r"(af[mt][1]), "r"(af[mt][2]), "r"(af[mt][3]),
                          "r"(bf_[nt][0]), "r"(bf_[nt][1]));
                }
        }
    };

    LOAD(0); STORE(0); __syncthreads();
    for (int s = 0; s < 64; s++) {
        int cur = s & 1;
        if (s < 63) LOAD(s + 1);
        COMPUTE(cur);
        if (s < 63) STORE(cur ^ 1);
        __syncthreads();
    }

    // epilogue: scale by DV2_i * DV2_j, coalesced float2 stores
    #pragma unroll
    for (int mt = 0; mt < 4; mt++) {
        int row0 = i0 + wm * 64 + mt * 16 + r;
        int row1 = row0 + 8;
        float s0 = g_DV2[row0], s1 = g_DV2[row1];
        #pragma unroll
        for (int nt = 0; nt < 4; nt++) {
            int col = j0 + wn * 32 + nt * 8 + 2 * q;
            float t0 = g_DV2[col], t1 = g_DV2[col + 1];
            float2 v0 = make_float2(c[mt][nt][0] * s0 * t0, c[mt][nt][1] * s0 * t1);
            float2 v1 = make_float2(c[mt][nt][2] * s1 * t0, c[mt][nt][3] * s1 * t1);
            *(float2*)&G[(size_t)row0 * N_NODES + col] = v0;
            *(float2*)&G[(size_t)row1 * N_NODES + col] = v1;
        }
    }
}

// =====================================================================
extern "C" void kernel_launch(void* const* d_in, const int* in_sizes, int n_in,
                              void* d_out, int out_size)
{
    const float* x  = (const float*)d_in[0];
    const int*   y  = (const int*)d_in[1];
    const float* hp = (const float*)d_in[2];
    float* out = (float*)d_out;

    k_simi<<<dim3(N_NODES / 128, E_EDGES / 64), 256>>>(x, y, hp);
    k_select<<<E_EDGES, 256>>>();
    k_dv<<<N_NODES / 256, 256>>>();
    k_gemm<<<dim3(N_NODES / 128, N_NODES / 128), 256>>>(out);

    // hyper_x = x.reshape(N, d), appended after G
    size_t gElems = (size_t)N_NODES * N_NODES;
    if ((size_t)out_size >= gElems + (size_t)N_NODES * ZD) {
        cudaMemcpyAsync(out + gElems, x, (size_t)N_NODES * ZD * sizeof(float),
                        cudaMemcpyDeviceToDevice);
    }
}

// round 3
// speedup vs baseline: 6.4947x; 6.4947x over previous
#include <cuda_runtime.h>
#include <cuda_bf16.h>

#define E_EDGES 1024
#define N_NODES 8192
#define ZD      256
#define KK_RANK 819

// ---- scratch (device globals: allocation-free) ----
__device__ float          g_simi[E_EDGES * N_NODES];          // 32 MB [e][n]
__device__ unsigned short g_Bh[E_EDGES * N_NODES];            // 16 MB bf16 bits: H * w_hi
__device__ unsigned short g_Bl[E_EDGES * N_NODES];            // 16 MB bf16 bits: H * w_lo
__device__ float          g_DV2[N_NODES];

// =====================================================================
// Kernel 1: simi[e][n] = dot(hyper_params[y[e/16]*16 + e%16], x[n])  (fp32)
// =====================================================================
__global__ __launch_bounds__(256) void k_simi(
    const float* __restrict__ x, const int* __restrict__ y,
    const float* __restrict__ hp)
{
    __shared__ float As[32][65];
    __shared__ float Bs[32][129];
    const int be = blockIdx.y * 64;
    const int bn = blockIdx.x * 128;
    const int tid = threadIdx.x;
    const int ty = tid >> 4, tx = tid & 15;

    float acc[4][8];
    #pragma unroll
    for (int i = 0; i < 4; i++)
        #pragma unroll
        for (int j = 0; j < 8; j++) acc[i][j] = 0.f;

    for (int k0 = 0; k0 < ZD; k0 += 32) {
        #pragma unroll
        for (int p = 0; p < 2; p++) {
            int idx = tid + p * 256;
            int e   = idx >> 3;
            int k4  = (idx & 7) << 2;
            int ge  = be + e;
            int row = y[ge >> 4] * 16 + (ge & 15);
            float4 v = *(const float4*)(hp + (size_t)row * ZD + k0 + k4);
            As[k4+0][e] = v.x; As[k4+1][e] = v.y; As[k4+2][e] = v.z; As[k4+3][e] = v.w;
        }
        #pragma unroll
        for (int p = 0; p < 4; p++) {
            int idx = tid + p * 256;
            int n   = idx >> 3;
            int k4  = (idx & 7) << 2;
            float4 v = *(const float4*)(x + (size_t)(bn + n) * ZD + k0 + k4);
            Bs[k4+0][n] = v.x; Bs[k4+1][n] = v.y; Bs[k4+2][n] = v.z; Bs[k4+3][n] = v.w;
        }
        __syncthreads();
        #pragma unroll
        for (int k = 0; k < 32; k++) {
            float a[4], b[8];
            #pragma unroll
            for (int mi = 0; mi < 4; mi++) a[mi] = As[k][ty + 16 * mi];
            #pragma unroll
            for (int ni = 0; ni < 8; ni++) b[ni] = Bs[k][tx + 16 * ni];
            #pragma unroll
            for (int mi = 0; mi < 4; mi++)
                #pragma unroll
                for (int ni = 0; ni < 8; ni++)
                    acc[mi][ni] = fmaf(a[mi], b[ni], acc[mi][ni]);
        }
        __syncthreads();
    }
    #pragma unroll
    for (int mi = 0; mi < 4; mi++)
        #pragma unroll
        for (int ni = 0; ni < 8; ni++)
            g_simi[(size_t)(be + ty + 16 * mi) * N_NODES + bn + tx + 16 * ni] = acc[mi][ni];
}

// =====================================================================
// Kernel 2: per-edge exact radix select (819th largest), build Bh/Bl.
// =====================================================================
__global__ __launch_bounds__(256) void k_select()
{
    __shared__ unsigned su[N_NODES];
    __shared__ unsigned hist[256];
    __shared__ unsigned s_bin, s_r, s_above;

    const int e = blockIdx.x;
    const int t = threadIdx.x;
    const float* row = g_simi + (size_t)e * N_NODES;

    #pragma unroll 4
    for (int i = 0; i < 32; i++) {
        unsigned b = __float_as_uint(row[i * 256 + t]);
        su[i * 256 + t] = (b & 0x80000000u) ? ~b : (b | 0x80000000u);
    }
    if (t == 0) { s_r = KK_RANK; s_above = 0; }
    __syncthreads();

    unsigned prefix = 0, pmask = 0;
    for (int level = 0; level < 4; level++) {
        int shift = 24 - 8 * level;
        hist[t] = 0;
        __syncthreads();
        #pragma unroll 4
        for (int i = 0; i < 32; i++) {
            unsigned u = su[i * 256 + t];
            if ((u & pmask) == prefix) atomicAdd(&hist[(u >> shift) & 0xFFu], 1u);
        }
        __syncthreads();
        if (t == 0) {
            unsigned r = s_r, above = s_above;
            int b;
            for (b = 255; b >= 0; b--) {
                unsigned c = hist[b];
                if (c >= r) break;
                r -= c; above += c;
            }
            s_bin = (unsigned)b; s_r = r; s_above = above;
        }
        __syncthreads();
        prefix |= (s_bin << shift);
        pmask  |= (0xFFu << shift);
        __syncthreads();
    }

    const unsigned thr = prefix;
    const unsigned de  = s_above;
    float w = 1.0f / (float)de;
    __nv_bfloat16 whi = __float2bfloat16(w);
    __nv_bfloat16 wlo = __float2bfloat16(w - __bfloat162float(whi));
    unsigned short whiB = *(unsigned short*)&whi;
    unsigned short wloB = *(unsigned short*)&wlo;

    #pragma unroll 4
    for (int i = 0; i < 32; i++) {
        int n = i * 256 + t;
        bool g = su[n] > thr;
        g_Bh[(size_t)e * N_NODES + n] = g ? whiB : (unsigned short)0;
        g_Bl[(size_t)e * N_NODES + n] = g ? wloB : (unsigned short)0;
    }
}

// =====================================================================
// Kernel 3: DV2[n] = rsqrt( #edges containing n )
// =====================================================================
__global__ __launch_bounds__(256) void k_dv()
{
    int n = blockIdx.x * 256 + threadIdx.x;
    int cnt = 0;
    #pragma unroll 8
    for (int e = 0; e < E_EDGES; e++)
        cnt += (g_Bh[(size_t)e * N_NODES + n] != 0);
    g_DV2[n] = rsqrtf((float)cnt);
}

// =====================================================================
// Kernel 4: G = diag(DV2) * (H diag(1/DE) H^T) * diag(DV2)
// Upper-triangular blocks only (bj>=bi); mirror via smem transpose.
// Stage layout [k][col] (stride 136 shorts) + ldmatrix.x4.trans.
// A = H (shared by hi/lo halves); 2 MMAs per fragment pair.
// =====================================================================
#define SSTRIDE 136
#define SBUF    (32 * SSTRIDE)

__device__ __forceinline__ void ldsm4t(unsigned &r0, unsigned &r1,
                                       unsigned &r2, unsigned &r3, unsigned a)
{
    asm volatile("ldmatrix.sync.aligned.m8n8.x4.trans.shared.b16 {%0,%1,%2,%3}, [%4];"
                 : "=r"(r0), "=r"(r1), "=r"(r2), "=r"(r3) : "r"(a));
}

__global__ __launch_bounds__(256, 1) void k_gemm(float* __restrict__ G)
{
    const int bi = blockIdx.y, bj = blockIdx.x;
    if (bj < bi) return;

    extern __shared__ char dynsm[];
    unsigned short* sA  = (unsigned short*)dynsm;            // [2][32][136]
    unsigned short* sBh = sA  + 2 * SBUF;
    unsigned short* sBl = sBh + 2 * SBUF;
    float*          sT  = (float*)dynsm;                      // [128][132] (j,i) reuse

    const int i0 = bi * 128, j0 = bj * 128;
    const int tid  = threadIdx.x;
    const int lane = tid & 31, warp = tid >> 5;
    const int wm = warp >> 2, wn = warp & 3;
    const int r = lane >> 2, q = lane & 3;

    float c[4][4][4];
    #pragma unroll
    for (int a = 0; a < 4; a++)
        #pragma unroll
        for (int b = 0; b < 4; b++)
            #pragma unroll
            for (int d = 0; d < 4; d++) c[a][b][d] = 0.f;

    // stage-load mapping: thread handles (kk = warp + 8p, cols 4*lane..+3)
    const int c4 = 4 * lane;
    ushort4 av[4], bh4[4], bl4[4];

    auto LOAD = [&](int kt) {
        #pragma unroll
        for (int p = 0; p < 4; p++) {
            int e = kt * 32 + warp + 8 * p;
            const size_t rowOff = (size_t)e * N_NODES;
            av[p]  = *(const ushort4*)(g_Bh + rowOff + i0 + c4);
            bh4[p] = *(const ushort4*)(g_Bh + rowOff + j0 + c4);
            bl4[p] = *(const ushort4*)(g_Bl + rowOff + j0 + c4);
        }
    };
    auto STORE = [&](int buf) {
        const unsigned short ONE = 0x3F80;
        #pragma unroll
        for (int p = 0; p < 4; p++) {
            int off = (buf * 32 + warp + 8 * p) * SSTRIDE + c4;
            ushort4 a = av[p];
            a.x = a.x ? ONE : 0; a.y = a.y ? ONE : 0;
            a.z = a.z ? ONE : 0; a.w = a.w ? ONE : 0;
            *(ushort4*)(sA  + off) = a;
            *(ushort4*)(sBh + off) = bh4[p];
            *(ushort4*)(sBl + off) = bl4[p];
        }
    };

    // ldmatrix lane offsets
    const int a_koff = (lane & 7) + ((lane >> 4) << 3);
    const int a_moff = ((lane >> 3) & 1) << 3;
    const int b_koff = (lane & 7) + (((lane >> 3) & 1) << 3);
    const int b_noff = ((lane >> 4) & 1) << 3;
    const unsigned baseA  = (unsigned)__cvta_generic_to_shared(sA);
    const unsigned baseBh = (unsigned)__cvta_generic_to_shared(sBh);
    const unsigned baseBl = (unsigned)__cvta_generic_to_shared(sBl);

    auto COMPUTE = [&](int buf) {
        #pragma unroll
        for (int kh = 0; kh < 2; kh++) {
            const int kb = kh * 16;
            unsigned af[4][4];
            #pragma unroll
            for (int mt = 0; mt < 4; mt++) {
                unsigned adr = baseA +
                    (unsigned)(((buf * 32 + kb + a_koff) * SSTRIDE +
                                wm * 64 + mt * 16 + a_moff) * 2);
                ldsm4t(af[mt][0], af[mt][1], af[mt][2], af[mt][3], adr);
            }
            unsigned bh_[4][2], bl_[4][2];
            #pragma unroll
            for (int pr = 0; pr < 2; pr++) {
                unsigned off = (unsigned)(((buf * 32 + kb + b_koff) * SSTRIDE +
                                           wn * 32 + pr * 16 + b_noff) * 2);
                unsigned r0, r1, r2, r3;
                ldsm4t(r0, r1, r2, r3, baseBh + off);
                bh_[2*pr][0] = r0; bh_[2*pr][1] = r1;
                bh_[2*pr+1][0] = r2; bh_[2*pr+1][1] = r3;
                ldsm4t(r0, r1, r2, r3, baseBl + off);
                bl_[2*pr][0] = r0; bl_[2*pr][1] = r1;
                bl_[2*pr+1][0] = r2; bl_[2*pr+1][1] = r3;
            }
            #pragma unroll
            for (int mt = 0; mt < 4; mt++)
                #pragma unroll
                for (int nt = 0; nt < 4; nt++) {
                    asm volatile(
                        "mma.sync.aligned.m16n8k16.row.col.f32.bf16.bf16.f32 "
                        "{%0,%1,%2,%3},{%4,%5,%6,%7},{%8,%9},{%0,%1,%2,%3};\n"
                        : "+f"(c[mt][nt][0]), "+f"(c[mt][nt][1]),
                          "+f"(c[mt][nt][2]), "+f"(c[mt][nt][3])
                        : "r"(af[mt][0]), "r"(af[mt][1]), "r"(af[mt][2]), "r"(af[mt][3]),
                          "r"(bh_[nt][0]), "r"(bh_[nt][1]));
                    asm volatile(
                        "mma.sync.aligned.m16n8k16.row.col.f32.bf16.bf16.f32 "
                        "{%0,%1,%2,%3},{%4,%5,%6,%7},{%8,%9},{%0,%1,%2,%3};\n"
                        : "+f"(c[mt][nt][0]), "+f"(c[mt][nt][1]),
                          "+f"(c[mt][nt][2]), "+f"(c[mt][nt][3])
                        : "r"(af[mt][0]), "r"(af[mt][1]), "r"(af[mt][2]), "r"(af[mt][3]),
                          "r"(bl_[nt][0]), "r"(bl_[nt][1]));
                }
        }
    };

    LOAD(0); STORE(0); __syncthreads();
    for (int kt = 0; kt < 32; kt++) {
        int cur = kt & 1;
        if (kt < 31) LOAD(kt + 1);
        COMPUTE(cur);
        if (kt < 31) STORE(cur ^ 1);
        __syncthreads();
    }

    // ---- epilogue: scale, store block, stage transpose for mirror ----
    const bool offd = (bi != bj);
    #pragma unroll
    for (int mt = 0; mt < 4; mt++) {
        int rl0 = wm * 64 + mt * 16 + r;
        int rl1 = rl0 + 8;
        float s0 = g_DV2[i0 + rl0], s1 = g_DV2[i0 + rl1];
        #pragma unroll
        for (int nt = 0; nt < 4; nt++) {
            int cl = wn * 32 + nt * 8 + 2 * q;
            float t0 = g_DV2[j0 + cl], t1 = g_DV2[j0 + cl + 1];
            float v00 = c[mt][nt][0] * s0 * t0;
            float v01 = c[mt][nt][1] * s0 * t1;
            float v10 = c[mt][nt][2] * s1 * t0;
            float v11 = c[mt][nt][3] * s1 * t1;
            *(float2*)&G[(size_t)(i0 + rl0) * N_NODES + j0 + cl] = make_float2(v00, v01);
            *(float2*)&G[(size_t)(i0 + rl1) * N_NODES + j0 + cl] = make_float2(v10, v11);
            if (offd) {
                sT[(cl    ) * 132 + rl0] = v00;
                sT[(cl + 1) * 132 + rl0] = v01;
                sT[(cl    ) * 132 + rl1] = v10;
                sT[(cl + 1) * 132 + rl1] = v11;
            }
        }
    }
    if (offd) {
        __syncthreads();
        #pragma unroll
        for (int t2 = tid; t2 < 4096; t2 += 256) {
            int jr = t2 >> 5;
            int ic = (t2 & 31) << 2;
            float4 v = *(const float4*)&sT[jr * 132 + ic];
            *(float4*)&G[(size_t)(j0 + jr) * N_NODES + i0 + ic] = v;
        }
    }
}

// =====================================================================
extern "C" void kernel_launch(void* const* d_in, const int* in_sizes, int n_in,
                              void* d_out, int out_size)
{
    const float* x  = (const float*)d_in[0];
    const int*   y  = (const int*)d_in[1];
    const float* hp = (const float*)d_in[2];
    float* out = (float*)d_out;

    const int smemBytes = 132 * 128 * (int)sizeof(float);    // 67584 >= 52224 stage
    cudaFuncSetAttribute(k_gemm, cudaFuncAttributeMaxDynamicSharedMemorySize, smemBytes);

    k_simi<<<dim3(N_NODES / 128, E_EDGES / 64), 256>>>(x, y, hp);
    k_select<<<E_EDGES, 256>>>();
    k_dv<<<N_NODES / 256, 256>>>();
    k_gemm<<<dim3(64, 64), 256, smemBytes>>>(out);

    size_t gElems = (size_t)N_NODES * N_NODES;
    if ((size_t)out_size >= gElems + (size_t)N_NODES * ZD) {
        cudaMemcpyAsync(out + gElems, x, (size_t)N_NODES * ZD * sizeof(float),
                        cudaMemcpyDeviceToDevice);
    }
}

// round 4
// speedup vs baseline: 6.4962x; 1.0002x over previous
#include <cuda_runtime.h>
#include <cuda_bf16.h>

#define E_EDGES 1024
#define N_NODES 8192
#define ZD      256
#define KK_RANK 819

// ---- scratch (device globals: allocation-free) ----
__device__ float          g_simi[E_EDGES * N_NODES];          // 32 MB [e][n]
__device__ unsigned short g_Bh[E_EDGES * N_NODES];            // 16 MB bf16 bits: H * w_hi
__device__ unsigned short g_Bl[E_EDGES * N_NODES];            // 16 MB bf16 bits: H * w_lo
__device__ float          g_DV2[N_NODES];

// =====================================================================
// Kernel 1: simi[e][n] = dot(hyper_params[y[e/16]*16 + e%16], x[n])  (fp32)
// =====================================================================
__global__ __launch_bounds__(256) void k_simi(
    const float* __restrict__ x, const int* __restrict__ y,
    const float* __restrict__ hp)
{
    __shared__ float As[32][65];
    __shared__ float Bs[32][129];
    const int be = blockIdx.y * 64;
    const int bn = blockIdx.x * 128;
    const int tid = threadIdx.x;
    const int ty = tid >> 4, tx = tid & 15;

    float acc[4][8];
    #pragma unroll
    for (int i = 0; i < 4; i++)
        #pragma unroll
        for (int j = 0; j < 8; j++) acc[i][j] = 0.f;

    for (int k0 = 0; k0 < ZD; k0 += 32) {
        #pragma unroll
        for (int p = 0; p < 2; p++) {
            int idx = tid + p * 256;
            int e   = idx >> 3;
            int k4  = (idx & 7) << 2;
            int ge  = be + e;
            int row = y[ge >> 4] * 16 + (ge & 15);
            float4 v = *(const float4*)(hp + (size_t)row * ZD + k0 + k4);
            As[k4+0][e] = v.x; As[k4+1][e] = v.y; As[k4+2][e] = v.z; As[k4+3][e] = v.w;
        }
        #pragma unroll
        for (int p = 0; p < 4; p++) {
            int idx = tid + p * 256;
            int n   = idx >> 3;
            int k4  = (idx & 7) << 2;
            float4 v = *(const float4*)(x + (size_t)(bn + n) * ZD + k0 + k4);
            Bs[k4+0][n] = v.x; Bs[k4+1][n] = v.y; Bs[k4+2][n] = v.z; Bs[k4+3][n] = v.w;
        }
        __syncthreads();
        #pragma unroll
        for (int k = 0; k < 32; k++) {
            float a[4], b[8];
            #pragma unroll
            for (int mi = 0; mi < 4; mi++) a[mi] = As[k][ty + 16 * mi];
            #pragma unroll
            for (int ni = 0; ni < 8; ni++) b[ni] = Bs[k][tx + 16 * ni];
            #pragma unroll
            for (int mi = 0; mi < 4; mi++)
                #pragma unroll
                for (int ni = 0; ni < 8; ni++)
                    acc[mi][ni] = fmaf(a[mi], b[ni], acc[mi][ni]);
        }
        __syncthreads();
    }
    #pragma unroll
    for (int mi = 0; mi < 4; mi++)
        #pragma unroll
        for (int ni = 0; ni < 8; ni++)
            g_simi[(size_t)(be + ty + 16 * mi) * N_NODES + bn + tx + 16 * ni] = acc[mi][ni];
}

// =====================================================================
// Kernel 2: per-edge exact radix select (819th largest), build Bh/Bl.
// =====================================================================
__global__ __launch_bounds__(256) void k_select()
{
    __shared__ unsigned su[N_NODES];
    __shared__ unsigned hist[256];
    __shared__ unsigned s_bin, s_r, s_above;

    const int e = blockIdx.x;
    const int t = threadIdx.x;
    const float* row = g_simi + (size_t)e * N_NODES;

    #pragma unroll 4
    for (int i = 0; i < 32; i++) {
        unsigned b = __float_as_uint(row[i * 256 + t]);
        su[i * 256 + t] = (b & 0x80000000u) ? ~b : (b | 0x80000000u);
    }
    if (t == 0) { s_r = KK_RANK; s_above = 0; }
    __syncthreads();

    unsigned prefix = 0, pmask = 0;
    for (int level = 0; level < 4; level++) {
        int shift = 24 - 8 * level;
        hist[t] = 0;
        __syncthreads();
        #pragma unroll 4
        for (int i = 0; i < 32; i++) {
            unsigned u = su[i * 256 + t];
            if ((u & pmask) == prefix) atomicAdd(&hist[(u >> shift) & 0xFFu], 1u);
        }
        __syncthreads();
        if (t == 0) {
            unsigned r = s_r, above = s_above;
            int b;
            for (b = 255; b >= 0; b--) {
                unsigned c = hist[b];
                if (c >= r) break;
                r -= c; above += c;
            }
            s_bin = (unsigned)b; s_r = r; s_above = above;
        }
        __syncthreads();
        prefix |= (s_bin << shift);
        pmask  |= (0xFFu << shift);
        __syncthreads();
    }

    const unsigned thr = prefix;
    const unsigned de  = s_above;
    float w = 1.0f / (float)de;
    __nv_bfloat16 whi = __float2bfloat16(w);
    __nv_bfloat16 wlo = __float2bfloat16(w - __bfloat162float(whi));
    unsigned short whiB = *(unsigned short*)&whi;
    unsigned short wloB = *(unsigned short*)&wlo;

    #pragma unroll 4
    for (int i = 0; i < 32; i++) {
        int n = i * 256 + t;
        bool g = su[n] > thr;
        g_Bh[(size_t)e * N_NODES + n] = g ? whiB : (unsigned short)0;
        g_Bl[(size_t)e * N_NODES + n] = g ? wloB : (unsigned short)0;
    }
}

// =====================================================================
// Kernel 3: DV2[n] = rsqrt( #edges containing n )
// =====================================================================
__global__ __launch_bounds__(256) void k_dv()
{
    int n = blockIdx.x * 256 + threadIdx.x;
    int cnt = 0;
    #pragma unroll 8
    for (int e = 0; e < E_EDGES; e++)
        cnt += (g_Bh[(size_t)e * N_NODES + n] != 0);
    g_DV2[n] = rsqrtf((float)cnt);
}

// =====================================================================
// Kernel 4: G = diag(DV2) * (H diag(1/DE) H^T) * diag(DV2)
// Upper-triangular blocks only (bj>=bi); mirror via smem transpose.
// Stage layout [k][col] (stride 136 shorts) + ldmatrix.x4.trans.
// A = H (shared by hi/lo halves); 2 MMAs per fragment pair.
// =====================================================================
#define SSTRIDE 136
#define SBUF    (32 * SSTRIDE)

__device__ __forceinline__ void ldsm4t(unsigned &r0, unsigned &r1,
                                       unsigned &r2, unsigned &r3, unsigned a)
{
    asm volatile("ldmatrix.sync.aligned.m8n8.x4.trans.shared.b16 {%0,%1,%2,%3}, [%4];"
                 : "=r"(r0), "=r"(r1), "=r"(r2), "=r"(r3) : "r"(a));
}

__global__ __launch_bounds__(256, 1) void k_gemm(float* __restrict__ G)
{
    const int bi = blockIdx.y, bj = blockIdx.x;
    if (bj < bi) return;

    extern __shared__ char dynsm[];
    unsigned short* sA  = (unsigned short*)dynsm;            // [2][32][136]
    unsigned short* sBh = sA  + 2 * SBUF;
    unsigned short* sBl = sBh + 2 * SBUF;
    float*          sT  = (float*)dynsm;                      // [128][132] (j,i) reuse

    const int i0 = bi * 128, j0 = bj * 128;
    const int tid  = threadIdx.x;
    const int lane = tid & 31, warp = tid >> 5;
    const int wm = warp >> 2, wn = warp & 3;
    const int r = lane >> 2, q = lane & 3;

    float c[4][4][4];
    #pragma unroll
    for (int a = 0; a < 4; a++)
        #pragma unroll
        for (int b = 0; b < 4; b++)
            #pragma unroll
            for (int d = 0; d < 4; d++) c[a][b][d] = 0.f;

    // stage-load mapping: thread handles (kk = warp + 8p, cols 4*lane..+3)
    const int c4 = 4 * lane;
    ushort4 av[4], bh4[4], bl4[4];

    auto LOAD = [&](int kt) {
        #pragma unroll
        for (int p = 0; p < 4; p++) {
            int e = kt * 32 + warp + 8 * p;
            const size_t rowOff = (size_t)e * N_NODES;
            av[p]  = *(const ushort4*)(g_Bh + rowOff + i0 + c4);
            bh4[p] = *(const ushort4*)(g_Bh + rowOff + j0 + c4);
            bl4[p] = *(const ushort4*)(g_Bl + rowOff + j0 + c4);
        }
    };
    auto STORE = [&](int buf) {
        const unsigned short ONE = 0x3F80;
        #pragma unroll
        for (int p = 0; p < 4; p++) {
            int off = (buf * 32 + warp + 8 * p) * SSTRIDE + c4;
            ushort4 a = av[p];
            a.x = a.x ? ONE : 0; a.y = a.y ? ONE : 0;
            a.z = a.z ? ONE : 0; a.w = a.w ? ONE : 0;
            *(ushort4*)(sA  + off) = a;
            *(ushort4*)(sBh + off) = bh4[p];
            *(ushort4*)(sBl + off) = bl4[p];
        }
    };

    // ldmatrix lane offsets
    const int a_koff = (lane & 7) + ((lane >> 4) << 3);
    const int a_moff = ((lane >> 3) & 1) << 3;
    const int b_koff = (lane & 7) + (((lane >> 3) & 1) << 3);
    const int b_noff = ((lane >> 4) & 1) << 3;
    const unsigned baseA  = (unsigned)__cvta_generic_to_shared(sA);
    const unsigned baseBh = (unsigned)__cvta_generic_to_shared(sBh);
    const unsigned baseBl = (unsigned)__cvta_generic_to_shared(sBl);

    auto COMPUTE = [&](int buf) {
        #pragma unroll
        for (int kh = 0; kh < 2; kh++) {
            const int kb = kh * 16;
            unsigned af[4][4];
            #pragma unroll
            for (int mt = 0; mt < 4; mt++) {
                unsigned adr = baseA +
                    (unsigned)(((buf * 32 + kb + a_koff) * SSTRIDE +
                                wm * 64 + mt * 16 + a_moff) * 2);
                ldsm4t(af[mt][0], af[mt][1], af[mt][2], af[mt][3], adr);
            }
            unsigned bh_[4][2], bl_[4][2];
            #pragma unroll
            for (int pr = 0; pr < 2; pr++) {
                unsigned off = (unsigned)(((buf * 32 + kb + b_koff) * SSTRIDE +
                                           wn * 32 + pr * 16 + b_noff) * 2);
                unsigned r0, r1, r2, r3;
                ldsm4t(r0, r1, r2, r3, baseBh + off);
                bh_[2*pr][0] = r0; bh_[2*pr][1] = r1;
                bh_[2*pr+1][0] = r2; bh_[2*pr+1][1] = r3;
                ldsm4t(r0, r1, r2, r3, baseBl + off);
                bl_[2*pr][0] = r0; bl_[2*pr][1] = r1;
                bl_[2*pr+1][0] = r2; bl_[2*pr+1][1] = r3;
            }
            #pragma unroll
            for (int mt = 0; mt < 4; mt++)
                #pragma unroll
                for (int nt = 0; nt < 4; nt++) {
                    asm volatile(
                        "mma.sync.aligned.m16n8k16.row.col.f32.bf16.bf16.f32 "
                        "{%0,%1,%2,%3},{%4,%5,%6,%7},{%8,%9},{%0,%1,%2,%3};\n"
                        : "+f"(c[mt][nt][0]), "+f"(c[mt][nt][1]),
                          "+f"(c[mt][nt][2]), "+f"(c[mt][nt][3])
                        : "r"(af[mt][0]), "r"(af[mt][1]), "r"(af[mt][2]), "r"(af[mt][3]),
                          "r"(bh_[nt][0]), "r"(bh_[nt][1]));
                    asm volatile(
                        "mma.sync.aligned.m16n8k16.row.col.f32.bf16.bf16.f32 "
                        "{%0,%1,%2,%3},{%4,%5,%6,%7},{%8,%9},{%0,%1,%2,%3};\n"
                        : "+f"(c[mt][nt][0]), "+f"(c[mt][nt][1]),
                          "+f"(c[mt][nt][2]), "+f"(c[mt][nt][3])
                        : "r"(af[mt][0]), "r"(af[mt][1]), "r"(af[mt][2]), "r"(af[mt][3]),
                          "r"(bl_[nt][0]), "r"(bl_[nt][1]));
                }
        }
    };

    LOAD(0); STORE(0); __syncthreads();
    for (int kt = 0; kt < 32; kt++) {
        int cur = kt & 1;
        if (kt < 31) LOAD(kt + 1);
        COMPUTE(cur);
        if (kt < 31) STORE(cur ^ 1);
        __syncthreads();
    }

    // ---- epilogue: scale, store block, stage transpose for mirror ----
    const bool offd = (bi != bj);
    #pragma unroll
    for (int mt = 0; mt < 4; mt++) {
        int rl0 = wm * 64 + mt * 16 + r;
        int rl1 = rl0 + 8;
        float s0 = g_DV2[i0 + rl0], s1 = g_DV2[i0 + rl1];
        #pragma unroll
        for (int nt = 0; nt < 4; nt++) {
            int cl = wn * 32 + nt * 8 + 2 * q;
            float t0 = g_DV2[j0 + cl], t1 = g_DV2[j0 + cl + 1];
            float v00 = c[mt][nt][0] * s0 * t0;
            float v01 = c[mt][nt][1] * s0 * t1;
            float v10 = c[mt][nt][2] * s1 * t0;
            float v11 = c[mt][nt][3] * s1 * t1;
            *(float2*)&G[(size_t)(i0 + rl0) * N_NODES + j0 + cl] = make_float2(v00, v01);
            *(float2*)&G[(size_t)(i0 + rl1) * N_NODES + j0 + cl] = make_float2(v10, v11);
            if (offd) {
                sT[(cl    ) * 132 + rl0] = v00;
                sT[(cl + 1) * 132 + rl0] = v01;
                sT[(cl    ) * 132 + rl1] = v10;
                sT[(cl + 1) * 132 + rl1] = v11;
            }
        }
    }
    if (offd) {
        __syncthreads();
        #pragma unroll
        for (int t2 = tid; t2 < 4096; t2 += 256) {
            int jr = t2 >> 5;
            int ic = (t2 & 31) << 2;
            float4 v = *(const float4*)&sT[jr * 132 + ic];
            *(float4*)&G[(size_t)(j0 + jr) * N_NODES + i0 + ic] = v;
        }
    }
}

// =====================================================================
extern "C" void kernel_launch(void* const* d_in, const int* in_sizes, int n_in,
                              void* d_out, int out_size)
{
    const float* x  = (const float*)d_in[0];
    const int*   y  = (const int*)d_in[1];
    const float* hp = (const float*)d_in[2];
    float* out = (float*)d_out;

    const int smemBytes = 132 * 128 * (int)sizeof(float);    // 67584 >= 52224 stage
    cudaFuncSetAttribute(k_gemm, cudaFuncAttributeMaxDynamicSharedMemorySize, smemBytes);

    k_simi<<<dim3(N_NODES / 128, E_EDGES / 64), 256>>>(x, y, hp);
    k_select<<<E_EDGES, 256>>>();
    k_dv<<<N_NODES / 256, 256>>>();
    k_gemm<<<dim3(64, 64), 256, smemBytes>>>(out);

    size_t gElems = (size_t)N_NODES * N_NODES;
    if ((size_t)out_size >= gElems + (size_t)N_NODES * ZD) {
        cudaMemcpyAsync(out + gElems, x, (size_t)N_NODES * ZD * sizeof(float),
                        cudaMemcpyDeviceToDevice);
    }
}

// round 6
// speedup vs baseline: 6.9887x; 1.0758x over previous
#include <cuda_runtime.h>
#include <cuda_bf16.h>
#include <cstdint>

#define E_EDGES 1024
#define N_NODES 8192
#define ZD      256
#define KK_RANK 819
#define DE_NOM  818
#define W0      (1.0f/818.0f)

// ---- scratch ----
__device__ float         g_simi[(size_t)E_EDGES * N_NODES];   // 32 MB [e][n]
__device__ unsigned      g_Hbt[256 * E_EDGES];                // bitmask [n/32][e]
__device__ unsigned char g_H8[(size_t)N_NODES * E_EDGES];     // s8 {0,1} H^T [n][e]
__device__ float         g_DV2[N_NODES];
__device__ int           g_nDev;
__device__ int           g_devE[E_EDGES];
__device__ int           g_devDE[E_EDGES];

__device__ __forceinline__ uint32_t smem_u32(const void* p) {
    uint32_t a;
    asm("{ .reg .u64 t; cvta.to.shared.u64 t, %1; cvt.u32.u64 %0, t; }" : "=r"(a) : "l"(p));
    return a;
}
__device__ __forceinline__ void ldsm4(unsigned &r0, unsigned &r1,
                                      unsigned &r2, unsigned &r3, unsigned a)
{
    asm volatile("ldmatrix.sync.aligned.m8n8.x4.shared.b16 {%0,%1,%2,%3}, [%4];"
                 : "=r"(r0), "=r"(r1), "=r"(r2), "=r"(r3) : "r"(a));
}
__device__ __forceinline__ void imma(int c[4], unsigned a0, unsigned a1,
                                     unsigned a2, unsigned a3, unsigned b0, unsigned b1)
{
    asm volatile("mma.sync.aligned.m16n8k32.row.col.s32.s8.s8.s32 "
                 "{%0,%1,%2,%3},{%4,%5,%6,%7},{%8,%9},{%0,%1,%2,%3};"
                 : "+r"(c[0]), "+r"(c[1]), "+r"(c[2]), "+r"(c[3])
                 : "r"(a0), "r"(a1), "r"(a2), "r"(a3), "r"(b0), "r"(b1));
}

// =====================================================================
// Kernel 1: simi = hyper_clss @ x^T  (fp32 SIMT GEMM)
// =====================================================================
__global__ __launch_bounds__(256) void k_simi(
    const float* __restrict__ x, const int* __restrict__ y,
    const float* __restrict__ hp)
{
    if (blockIdx.x == 0 && blockIdx.y == 0 && threadIdx.x == 0) g_nDev = 0;

    __shared__ float As[32][65];
    __shared__ float Bs[32][129];
    const int be = blockIdx.y * 64, bn = blockIdx.x * 128;
    const int tid = threadIdx.x;
    const int ty = tid >> 4, tx = tid & 15;

    float acc[4][8];
    #pragma unroll
    for (int i = 0; i < 4; i++)
        #pragma unroll
        for (int j = 0; j < 8; j++) acc[i][j] = 0.f;

    for (int k0 = 0; k0 < ZD; k0 += 32) {
        #pragma unroll
        for (int p = 0; p < 2; p++) {
            int idx = tid + p * 256;
            int e = idx >> 3, k4 = (idx & 7) << 2;
            int ge = be + e;
            int row = y[ge >> 4] * 16 + (ge & 15);
            float4 v = *(const float4*)(hp + (size_t)row * ZD + k0 + k4);
            As[k4+0][e] = v.x; As[k4+1][e] = v.y; As[k4+2][e] = v.z; As[k4+3][e] = v.w;
        }
        #pragma unroll
        for (int p = 0; p < 4; p++) {
            int idx = tid + p * 256;
            int n = idx >> 3, k4 = (idx & 7) << 2;
            float4 v = *(const float4*)(x + (size_t)(bn + n) * ZD + k0 + k4);
            Bs[k4+0][n] = v.x; Bs[k4+1][n] = v.y; Bs[k4+2][n] = v.z; Bs[k4+3][n] = v.w;
        }
        __syncthreads();
        #pragma unroll
        for (int k = 0; k < 32; k++) {
            float a[4], b[8];
            #pragma unroll
            for (int mi = 0; mi < 4; mi++) a[mi] = As[k][ty + 16 * mi];
            #pragma unroll
            for (int ni = 0; ni < 8; ni++) b[ni] = Bs[k][tx + 16 * ni];
            #pragma unroll
            for (int mi = 0; mi < 4; mi++)
                #pragma unroll
                for (int ni = 0; ni < 8; ni++)
                    acc[mi][ni] = fmaf(a[mi], b[ni], acc[mi][ni]);
        }
        __syncthreads();
    }
    #pragma unroll
    for (int mi = 0; mi < 4; mi++)
        #pragma unroll
        for (int ni = 0; ni < 8; ni++)
            g_simi[(size_t)(be + ty + 16 * mi) * N_NODES + bn + tx + 16 * ni] = acc[mi][ni];
}

// =====================================================================
// Kernel 2: exact radix select -> bitmask H^T + deviant-edge record
// =====================================================================
__global__ __launch_bounds__(256) void k_select()
{
    __shared__ unsigned su[N_NODES];
    __shared__ unsigned hist[256];
    __shared__ unsigned s_bin, s_r, s_above;

    const int e = blockIdx.x;
    const int t = threadIdx.x;
    const float* row = g_simi + (size_t)e * N_NODES;

    #pragma unroll 4
    for (int i = 0; i < 32; i++) {
        unsigned b = __float_as_uint(row[i * 256 + t]);
        su[i * 256 + t] = (b & 0x80000000u) ? ~b : (b | 0x80000000u);
    }
    if (t == 0) { s_r = KK_RANK; s_above = 0; }
    __syncthreads();

    unsigned prefix = 0, pmask = 0;
    for (int level = 0; level < 4; level++) {
        int shift = 24 - 8 * level;
        hist[t] = 0;
        __syncthreads();
        #pragma unroll 4
        for (int i = 0; i < 32; i++) {
            unsigned u = su[i * 256 + t];
            if ((u & pmask) == prefix) atomicAdd(&hist[(u >> shift) & 0xFFu], 1u);
        }
        __syncthreads();
        if (t == 0) {
            unsigned r = s_r, above = s_above;
            int b;
            for (b = 255; b >= 0; b--) {
                unsigned c = hist[b];
                if (c >= r) break;
                r -= c; above += c;
            }
            s_bin = (unsigned)b; s_r = r; s_above = above;
        }
        __syncthreads();
        prefix |= (s_bin << shift);
        pmask  |= (0xFFu << shift);
        __syncthreads();
    }

    const unsigned thr = prefix;
    const unsigned de  = s_above;

    unsigned v = 0;
    #pragma unroll
    for (int b = 0; b < 32; b++)
        v |= (su[32 * t + b] > thr) ? (1u << b) : 0u;
    g_Hbt[t * E_EDGES + e] = v;

    if (t == 0 && de != DE_NOM) {
        int idx = atomicAdd(&g_nDev, 1);
        g_devE[idx] = e; g_devDE[idx] = (int)de;
    }
}

// =====================================================================
// Kernel 3: bitmask -> s8 {0,1} g_H8[n][e]  (coalesced along e)
// =====================================================================
__global__ __launch_bounds__(256) void k_pack()
{
    const int w = blockIdx.x;           // node word 0..255
    const int tid = threadIdx.x;
    #pragma unroll
    for (int it = 0; it < 4; it++) {
        int e = it * 256 + tid;
        unsigned v = g_Hbt[w * E_EDGES + e];
        #pragma unroll
        for (int b = 0; b < 32; b++)
            g_H8[(size_t)(w * 32 + b) * E_EDGES + e] =
                ((v >> b) & 1u) ? (unsigned char)1 : (unsigned char)0;
    }
}

// =====================================================================
// Kernel 4: DV2[n] = rsqrt(popcount over edges)
// =====================================================================
__global__ __launch_bounds__(256) void k_dv()
{
    int n = blockIdx.x * 256 + threadIdx.x;
    int w = n >> 5, bit = n & 31;
    int cnt = 0;
    const unsigned* base = g_Hbt + (size_t)w * E_EDGES;
    #pragma unroll 8
    for (int e = 0; e < E_EDGES; e++)
        cnt += (base[e] >> bit) & 1u;
    g_DV2[n] = rsqrtf((float)cnt);
}

// =====================================================================
// Kernel 5: O = H^T H  (s8 IMMA, exact s32); G = W0*DV2i*DV2j*O
// 128x128 tile, K=1024 in 8 stages of 128 edge-bytes, double-buffered.
// Stage layout: [row][144B stride] -> conflict-free STS.128 + ldmatrix.x4
// =====================================================================
#define GSTR  144
#define GBUF  (128 * GSTR)   // 18432 B per stage buffer

__global__ __launch_bounds__(256, 1) void k_gemm(float* __restrict__ G)
{
    const int bi = blockIdx.y, bj = blockIdx.x;
    if (bj < bi) return;

    extern __shared__ char dynsm[];
    char*  sA = dynsm;                    // 2 x 18432
    char*  sB = dynsm + 2 * GBUF;         // 2 x 18432
    float* sT = (float*)dynsm;            // 128 x 132 floats (reuse)

    const int i0 = bi * 128, j0 = bj * 128;
    const int tid = threadIdx.x;
    const int lane = tid & 31, warp = tid >> 5;
    const int wm = warp >> 2, wn = warp & 3;         // 2 x 4 warp grid
    const int r = lane >> 2, q = lane & 3;

    int acc[4][4][4];
    #pragma unroll
    for (int a = 0; a < 4; a++)
        #pragma unroll
        for (int b = 0; b < 4; b++)
            #pragma unroll
            for (int d = 0; d < 4; d++) acc[a][b][d] = 0;

    uint4 av[4], bv[4];
    auto LOAD = [&](int s) {
        const int e0 = s * 128;
        #pragma unroll
        for (int p = 0; p < 4; p++) {
            int c = tid + p * 256;                   // 0..1023
            int row = c >> 3, ch = (c & 7) << 4;
            av[p] = *(const uint4*)(g_H8 + (size_t)(i0 + row) * E_EDGES + e0 + ch);
            bv[p] = *(const uint4*)(g_H8 + (size_t)(j0 + row) * E_EDGES + e0 + ch);
        }
    };
    auto STORE = [&](int buf) {
        #pragma unroll
        for (int p = 0; p < 4; p++) {
            int c = tid + p * 256;
            int row = c >> 3, ch = (c & 7) << 4;
            *(uint4*)(sA + buf * GBUF + row * GSTR + ch) = av[p];
            *(uint4*)(sB + buf * GBUF + row * GSTR + ch) = bv[p];
        }
    };

    const unsigned baseA = smem_u32(sA), baseB = smem_u32(sB);
    // ldmatrix lane address components
    const int a_row = lane & 15, a_off = (lane >> 4) << 4;
    const int b_row = ((lane >> 4) << 3) + (lane & 7);
    const int b_off = ((lane >> 3) & 1) << 4;

    auto COMPUTE = [&](int buf) {
        #pragma unroll
        for (int ks = 0; ks < 4; ks++) {             // 4 x k32 per stage
            const int koff = ks * 32;
            unsigned af[4][4], bf[2][4];
            #pragma unroll
            for (int mt = 0; mt < 4; mt++) {
                unsigned adr = baseA + buf * GBUF +
                    (unsigned)((wm * 64 + mt * 16 + a_row) * GSTR + koff + a_off);
                ldsm4(af[mt][0], af[mt][1], af[mt][2], af[mt][3], adr);
            }
            #pragma unroll
            for (int h = 0; h < 2; h++) {
                unsigned adr = baseB + buf * GBUF +
                    (unsigned)((wn * 32 + h * 16 + b_row) * GSTR + koff + b_off);
                ldsm4(bf[h][0], bf[h][1], bf[h][2], bf[h][3], adr);
            }
            #pragma unroll
            for (int mt = 0; mt < 4; mt++)
                #pragma unroll
                for (int nt = 0; nt < 4; nt++) {
                    const int h = nt >> 1, s2 = (nt & 1) << 1;
                    imma(acc[mt][nt], af[mt][0], af[mt][1], af[mt][2], af[mt][3],
                         bf[h][s2], bf[h][s2 + 1]);
                }
        }
    };

    LOAD(0); STORE(0); __syncthreads();
    for (int s = 0; s < 8; s++) {
        int cur = s & 1;
        if (s < 7) LOAD(s + 1);
        COMPUTE(cur);
        if (s < 7) STORE(cur ^ 1);
        __syncthreads();
    }

    // ---- epilogue: scale, store block, mirror via smem transpose ----
    const bool offd = (bi != bj);
    #pragma unroll
    for (int mt = 0; mt < 4; mt++) {
        int rl0 = wm * 64 + mt * 16 + r;
        int rl1 = rl0 + 8;
        float s0 = g_DV2[i0 + rl0] * W0, s1 = g_DV2[i0 + rl1] * W0;
        #pragma unroll
        for (int nt = 0; nt < 4; nt++) {
            int cl = wn * 32 + nt * 8 + 2 * q;
            float t0 = g_DV2[j0 + cl], t1 = g_DV2[j0 + cl + 1];
            float v00 = (float)acc[mt][nt][0] * s0 * t0;
            float v01 = (float)acc[mt][nt][1] * s0 * t1;
            float v10 = (float)acc[mt][nt][2] * s1 * t0;
            float v11 = (float)acc[mt][nt][3] * s1 * t1;
            *(float2*)&G[(size_t)(i0 + rl0) * N_NODES + j0 + cl] = make_float2(v00, v01);
            *(float2*)&G[(size_t)(i0 + rl1) * N_NODES + j0 + cl] = make_float2(v10, v11);
            if (offd) {
                sT[(cl    ) * 132 + rl0] = v00;
                sT[(cl + 1) * 132 + rl0] = v01;
                sT[(cl    ) * 132 + rl1] = v10;
                sT[(cl + 1) * 132 + rl1] = v11;
            }
        }
    }
    if (offd) {
        __syncthreads();
        #pragma unroll
        for (int t2 = tid; t2 < 4096; t2 += 256) {
            int jr = t2 >> 5, ic = (t2 & 31) << 2;
            float4 v = *(const float4*)&sT[jr * 132 + ic];
            *(float4*)&G[(size_t)(j0 + jr) * N_NODES + i0 + ic] = v;
        }
    }
}

// =====================================================================
// Kernel 6: exact correction for deviant edges (de != 818); usually no-op
// =====================================================================
__global__ __launch_bounds__(256) void k_fix(float* __restrict__ G)
{
    const int d = blockIdx.x;
    if (d >= g_nDev) return;
    const int e = g_devE[d];
    const int de = g_devDE[d];
    const float delta = 1.0f / (float)de - W0;

    __shared__ int mem[1024];
    __shared__ int cnt;
    if (threadIdx.x == 0) cnt = 0;
    __syncthreads();
    for (int n = threadIdx.x; n < N_NODES; n += 256)
        if (g_H8[(size_t)n * E_EDGES + e]) { int p = atomicAdd(&cnt, 1); mem[p] = n; }
    __syncthreads();
    const int m = cnt;
    for (int idx = threadIdx.x; idx < m * m; idx += 256) {
        int i = mem[idx / m], j = mem[idx % m];
        atomicAdd(&G[(size_t)i * N_NODES + j], delta * g_DV2[i] * g_DV2[j]);
    }
}

// =====================================================================
extern "C" void kernel_launch(void* const* d_in, const int* in_sizes, int n_in,
                              void* d_out, int out_size)
{
    const float* x  = (const float*)d_in[0];
    const int*   y  = (const int*)d_in[1];
    const float* hp = (const float*)d_in[2];
    float* out = (float*)d_out;

    const int smemBytes = 4 * GBUF;                 // 73728 (>= 67584 for sT)
    cudaFuncSetAttribute(k_gemm, cudaFuncAttributeMaxDynamicSharedMemorySize, smemBytes);

    k_simi<<<dim3(N_NODES / 128, E_EDGES / 64), 256>>>(x, y, hp);
    k_select<<<E_EDGES, 256>>>();
    k_pack<<<256, 256>>>();
    k_dv<<<N_NODES / 256, 256>>>();
    k_gemm<<<dim3(64, 64), 256, smemBytes>>>(out);
    k_fix<<<128, 256>>>(out);

    size_t gElems = (size_t)N_NODES * N_NODES;
    if ((size_t)out_size >= gElems + (size_t)N_NODES * ZD) {
        cudaMemcpyAsync(out + gElems, x, (size_t)N_NODES * ZD * sizeof(float),
                        cudaMemcpyDeviceToDevice);
    }
}

// round 7
// speedup vs baseline: 7.8979x; 1.1301x over previous
#include <cuda_runtime.h>
#include <cuda_bf16.h>
#include <cstdint>

#define E_EDGES 1024
#define N_NODES 8192
#define ZD      256
#define KK_RANK 819
#define DE_NOM  818
#define W0      (1.0f/818.0f)

// ---- scratch ----
__device__ float         g_simi[(size_t)E_EDGES * N_NODES];   // 32 MB [e][n]
__device__ unsigned      g_Hbt[256 * E_EDGES];                // bitmask [n/32][e]
__device__ unsigned char g_H8[(size_t)N_NODES * E_EDGES];     // s8 {0,1} H^T [n][e]
__device__ float         g_DV2[N_NODES];
__device__ int           g_nDev;
__device__ int           g_devE[E_EDGES];
__device__ int           g_devDE[E_EDGES];

__device__ __forceinline__ uint32_t smem_u32(const void* p) {
    uint32_t a;
    asm("{ .reg .u64 t; cvta.to.shared.u64 t, %1; cvt.u32.u64 %0, t; }" : "=r"(a) : "l"(p));
    return a;
}
__device__ __forceinline__ void ldsm4(unsigned &r0, unsigned &r1,
                                      unsigned &r2, unsigned &r3, unsigned a)
{
    asm volatile("ldmatrix.sync.aligned.m8n8.x4.shared.b16 {%0,%1,%2,%3}, [%4];"
                 : "=r"(r0), "=r"(r1), "=r"(r2), "=r"(r3) : "r"(a));
}
__device__ __forceinline__ void imma(int c[4], unsigned a0, unsigned a1,
                                     unsigned a2, unsigned a3, unsigned b0, unsigned b1)
{
    asm volatile("mma.sync.aligned.m16n8k32.row.col.s32.s8.s8.s32 "
                 "{%0,%1,%2,%3},{%4,%5,%6,%7},{%8,%9},{%0,%1,%2,%3};"
                 : "+r"(c[0]), "+r"(c[1]), "+r"(c[2]), "+r"(c[3])
                 : "r"(a0), "r"(a1), "r"(a2), "r"(a3), "r"(b0), "r"(b1));
}
#define CP16(dst, src) \
    asm volatile("cp.async.cg.shared.global [%0], [%1], 16;" :: "r"(dst), "l"(src) : "memory")
#define CP_COMMIT() asm volatile("cp.async.commit_group;" ::: "memory")
#define CP_WAIT0()  asm volatile("cp.async.wait_group 0;" ::: "memory")
#define CP_WAIT1()  asm volatile("cp.async.wait_group 1;" ::: "memory")

// =====================================================================
// Kernel 1: simi = hyper_clss @ x^T  (fp32 SIMT GEMM)
// =====================================================================
__global__ __launch_bounds__(256) void k_simi(
    const float* __restrict__ x, const int* __restrict__ y,
    const float* __restrict__ hp)
{
    if (blockIdx.x == 0 && blockIdx.y == 0 && threadIdx.x == 0) g_nDev = 0;

    __shared__ float As[32][65];
    __shared__ float Bs[32][129];
    const int be = blockIdx.y * 64, bn = blockIdx.x * 128;
    const int tid = threadIdx.x;
    const int ty = tid >> 4, tx = tid & 15;

    float acc[4][8];
    #pragma unroll
    for (int i = 0; i < 4; i++)
        #pragma unroll
        for (int j = 0; j < 8; j++) acc[i][j] = 0.f;

    for (int k0 = 0; k0 < ZD; k0 += 32) {
        #pragma unroll
        for (int p = 0; p < 2; p++) {
            int idx = tid + p * 256;
            int e = idx >> 3, k4 = (idx & 7) << 2;
            int ge = be + e;
            int row = y[ge >> 4] * 16 + (ge & 15);
            float4 v = *(const float4*)(hp + (size_t)row * ZD + k0 + k4);
            As[k4+0][e] = v.x; As[k4+1][e] = v.y; As[k4+2][e] = v.z; As[k4+3][e] = v.w;
        }
        #pragma unroll
        for (int p = 0; p < 4; p++) {
            int idx = tid + p * 256;
            int n = idx >> 3, k4 = (idx & 7) << 2;
            float4 v = *(const float4*)(x + (size_t)(bn + n) * ZD + k0 + k4);
            Bs[k4+0][n] = v.x; Bs[k4+1][n] = v.y; Bs[k4+2][n] = v.z; Bs[k4+3][n] = v.w;
        }
        __syncthreads();
        #pragma unroll
        for (int k = 0; k < 32; k++) {
            float a[4], b[8];
            #pragma unroll
            for (int mi = 0; mi < 4; mi++) a[mi] = As[k][ty + 16 * mi];
            #pragma unroll
            for (int ni = 0; ni < 8; ni++) b[ni] = Bs[k][tx + 16 * ni];
            #pragma unroll
            for (int mi = 0; mi < 4; mi++)
                #pragma unroll
                for (int ni = 0; ni < 8; ni++)
                    acc[mi][ni] = fmaf(a[mi], b[ni], acc[mi][ni]);
        }
        __syncthreads();
    }
    #pragma unroll
    for (int mi = 0; mi < 4; mi++)
        #pragma unroll
        for (int ni = 0; ni < 8; ni++)
            g_simi[(size_t)(be + ty + 16 * mi) * N_NODES + bn + tx + 16 * ni] = acc[mi][ni];
}

// =====================================================================
// Kernel 2: exact radix select (parallel suffix-scan per level)
// =====================================================================
__global__ __launch_bounds__(256) void k_select()
{
    __shared__ unsigned su[N_NODES];
    __shared__ unsigned hist[256];
    __shared__ unsigned sfx[256];
    __shared__ unsigned s_bin, s_r, s_above;

    const int e = blockIdx.x;
    const int t = threadIdx.x;
    const float* row = g_simi + (size_t)e * N_NODES;

    #pragma unroll 4
    for (int i = 0; i < 32; i++) {
        unsigned b = __float_as_uint(row[i * 256 + t]);
        su[i * 256 + t] = (b & 0x80000000u) ? ~b : (b | 0x80000000u);
    }
    if (t == 0) { s_r = KK_RANK; s_above = 0; }
    __syncthreads();

    unsigned prefix = 0, pmask = 0;
    for (int level = 0; level < 4; level++) {
        int shift = 24 - 8 * level;
        hist[t] = 0;
        __syncthreads();
        #pragma unroll 4
        for (int i = 0; i < 32; i++) {
            unsigned u = su[i * 256 + t];
            if ((u & pmask) == prefix) atomicAdd(&hist[(u >> shift) & 0xFFu], 1u);
        }
        __syncthreads();
        // inclusive suffix sum of hist
        sfx[t] = hist[t];
        __syncthreads();
        #pragma unroll
        for (int off = 1; off < 256; off <<= 1) {
            unsigned v = sfx[t] + ((t + off < 256) ? sfx[t + off] : 0u);
            __syncthreads();
            sfx[t] = v;
            __syncthreads();
        }
        unsigned r = s_r;
        unsigned nxt = (t < 255) ? sfx[t + 1] : 0u;
        if (sfx[t] >= r && nxt < r) {       // exactly one thread
            s_bin = (unsigned)t;
            s_r = r - nxt;
            s_above += nxt;
        }
        __syncthreads();
        prefix |= (s_bin << shift);
        pmask  |= (0xFFu << shift);
        __syncthreads();
    }

    const unsigned thr = prefix;
    const unsigned de  = s_above;

    unsigned v = 0;
    #pragma unroll
    for (int b = 0; b < 32; b++)
        v |= (su[32 * t + b] > thr) ? (1u << b) : 0u;
    g_Hbt[t * E_EDGES + e] = v;

    if (t == 0 && de != DE_NOM) {
        int idx = atomicAdd(&g_nDev, 1);
        g_devE[idx] = e; g_devDE[idx] = (int)de;
    }
}

// =====================================================================
// Kernel 3: bitmask -> s8 {0,1} + DV2 (fused). Block = node word w.
// =====================================================================
__global__ __launch_bounds__(256) void k_pack_dv()
{
    const int w = blockIdx.x;           // 0..255
    const int t = threadIdx.x;
    const int lane = t & 31;
    __shared__ int s_cnt[32];
    if (t < 32) s_cnt[t] = 0;
    __syncthreads();

    uint4 vv = *(const uint4*)&g_Hbt[w * E_EDGES + 4 * t];
    unsigned v[4] = {vv.x, vv.y, vv.z, vv.w};

    #pragma unroll
    for (int b = 0; b < 32; b++) {
        uchar4 c;
        c.x = (v[0] >> b) & 1u; c.y = (v[1] >> b) & 1u;
        c.z = (v[2] >> b) & 1u; c.w = (v[3] >> b) & 1u;
        *(uchar4*)&g_H8[(size_t)(w * 32 + b) * E_EDGES + 4 * t] = c;
        int cnt = 0;
        #pragma unroll
        for (int j = 0; j < 4; j++)
            cnt += __popc(__ballot_sync(0xFFFFFFFFu, (v[j] >> b) & 1u));
        if (lane == 0) atomicAdd(&s_cnt[b], cnt);
    }
    __syncthreads();
    if (t < 32) g_DV2[w * 32 + t] = rsqrtf((float)s_cnt[t]);
}

// =====================================================================
// Kernel 4: O = H^T H (s8 IMMA); G = W0*DV2i*DV2j*O
// Triangular grid (2080 blocks); cp.async double-buffer; 2 CTAs/SM.
// =====================================================================
#define GSTR  144
#define GBUF  (128 * GSTR)   // 18432 B

__global__ __launch_bounds__(256, 2) void k_gemm(float* __restrict__ G)
{
    // triangular decode: block b -> (bi, bj), bj >= bi
    int b = blockIdx.x;
    int bi = (int)(64.5f - sqrtf(64.5f * 64.5f - 2.0f * (float)b));
    while (64 * bi - bi * (bi - 1) / 2 > b) bi--;
    while (64 * (bi + 1) - (bi + 1) * bi / 2 <= b) bi++;
    const int bj = bi + (b - (64 * bi - bi * (bi - 1) / 2));

    extern __shared__ char dynsm[];
    char*  sA = dynsm;                    // 2 x 18432
    char*  sB = dynsm + 2 * GBUF;         // 2 x 18432
    float* sT = (float*)dynsm;            // 128 x 132 floats (reuse)

    const int i0 = bi * 128, j0 = bj * 128;
    const int tid = threadIdx.x;
    const int lane = tid & 31, warp = tid >> 5;
    const int wm = warp >> 2, wn = warp & 3;
    const int r = lane >> 2, q = lane & 3;

    int acc[4][4][4];
    #pragma unroll
    for (int a = 0; a < 4; a++)
        #pragma unroll
        for (int bb = 0; bb < 4; bb++)
            #pragma unroll
            for (int d = 0; d < 4; d++) acc[a][bb][d] = 0;

    const unsigned baseA = smem_u32(sA), baseB = smem_u32(sB);
    const int lrow = tid >> 3, lch = (tid & 7) << 4;   // fixed per-thread slice

    auto ISSUE = [&](int s, int buf) {
        const int e0 = s * 128;
        #pragma unroll
        for (int p = 0; p < 4; p++) {
            int row = lrow + p * 32;
            unsigned off = (unsigned)(buf * GBUF + row * GSTR + lch);
            CP16(baseA + off, g_H8 + (size_t)(i0 + row) * E_EDGES + e0 + lch);
            CP16(baseB + off, g_H8 + (size_t)(j0 + row) * E_EDGES + e0 + lch);
        }
        CP_COMMIT();
    };

    const int a_row = lane & 15, a_off = (lane >> 4) << 4;
    const int b_row = ((lane >> 4) << 3) + (lane & 7);
    const int b_off = ((lane >> 3) & 1) << 4;

    auto COMPUTE = [&](int buf) {
        #pragma unroll
        for (int ks = 0; ks < 4; ks++) {
            const int koff = ks * 32;
            unsigned af[4][4], bf[2][4];
            #pragma unroll
            for (int mt = 0; mt < 4; mt++) {
                unsigned adr = baseA + buf * GBUF +
                    (unsigned)((wm * 64 + mt * 16 + a_row) * GSTR + koff + a_off);
                ldsm4(af[mt][0], af[mt][1], af[mt][2], af[mt][3], adr);
            }
            #pragma unroll
            for (int h = 0; h < 2; h++) {
                unsigned adr = baseB + buf * GBUF +
                    (unsigned)((wn * 32 + h * 16 + b_row) * GSTR + koff + b_off);
                ldsm4(bf[h][0], bf[h][1], bf[h][2], bf[h][3], adr);
            }
            #pragma unroll
            for (int mt = 0; mt < 4; mt++)
                #pragma unroll
                for (int nt = 0; nt < 4; nt++) {
                    const int h = nt >> 1, s2 = (nt & 1) << 1;
                    imma(acc[mt][nt], af[mt][0], af[mt][1], af[mt][2], af[mt][3],
                         bf[h][s2], bf[h][s2 + 1]);
                }
        }
    };

    ISSUE(0, 0);
    ISSUE(1, 1);
    for (int s = 0; s < 8; s++) {
        if (s == 7) CP_WAIT0(); else CP_WAIT1();
        __syncthreads();
        COMPUTE(s & 1);
        __syncthreads();
        if (s + 2 < 8) ISSUE(s + 2, s & 1);
    }
    __syncthreads();

    // ---- epilogue: scale, store block, mirror via smem transpose ----
    const bool offd = (bi != bj);
    #pragma unroll
    for (int mt = 0; mt < 4; mt++) {
        int rl0 = wm * 64 + mt * 16 + r;
        int rl1 = rl0 + 8;
        float s0 = g_DV2[i0 + rl0] * W0, s1 = g_DV2[i0 + rl1] * W0;
        #pragma unroll
        for (int nt = 0; nt < 4; nt++) {
            int cl = wn * 32 + nt * 8 + 2 * q;
            float t0 = g_DV2[j0 + cl], t1 = g_DV2[j0 + cl + 1];
            float v00 = (float)acc[mt][nt][0] * s0 * t0;
            float v01 = (float)acc[mt][nt][1] * s0 * t1;
            float v10 = (float)acc[mt][nt][2] * s1 * t0;
            float v11 = (float)acc[mt][nt][3] * s1 * t1;
            *(float2*)&G[(size_t)(i0 + rl0) * N_NODES + j0 + cl] = make_float2(v00, v01);
            *(float2*)&G[(size_t)(i0 + rl1) * N_NODES + j0 + cl] = make_float2(v10, v11);
            if (offd) {
                sT[(cl    ) * 132 + rl0] = v00;
                sT[(cl + 1) * 132 + rl0] = v01;
                sT[(cl    ) * 132 + rl1] = v10;
                sT[(cl + 1) * 132 + rl1] = v11;
            }
        }
    }
    if (offd) {
        __syncthreads();
        #pragma unroll
        for (int t2 = tid; t2 < 4096; t2 += 256) {
            int jr = t2 >> 5, ic = (t2 & 31) << 2;
            float4 v = *(const float4*)&sT[jr * 132 + ic];
            *(float4*)&G[(size_t)(j0 + jr) * N_NODES + i0 + ic] = v;
        }
    }
}

// =====================================================================
// Kernel 5: exact correction for deviant edges (de != 818); usually no-op
// =====================================================================
__global__ __launch_bounds__(256) void k_fix(float* __restrict__ G)
{
    const int d = blockIdx.x;
    if (d >= g_nDev) return;
    const int e = g_devE[d];
    const int de = g_devDE[d];
    const float delta = 1.0f / (float)de - W0;

    __shared__ int mem[1024];
    __shared__ int cnt;
    if (threadIdx.x == 0) cnt = 0;
    __syncthreads();
    for (int n = threadIdx.x; n < N_NODES; n += 256)
        if (g_H8[(size_t)n * E_EDGES + e]) { int p = atomicAdd(&cnt, 1); mem[p] = n; }
    __syncthreads();
    const int m = cnt;
    for (int idx = threadIdx.x; idx < m * m; idx += 256) {
        int i = mem[idx / m], j = mem[idx % m];
        atomicAdd(&G[(size_t)i * N_NODES + j], delta * g_DV2[i] * g_DV2[j]);
    }
}

// =====================================================================
extern "C" void kernel_launch(void* const* d_in, const int* in_sizes, int n_in,
                              void* d_out, int out_size)
{
    const float* x  = (const float*)d_in[0];
    const int*   y  = (const int*)d_in[1];
    const float* hp = (const float*)d_in[2];
    float* out = (float*)d_out;

    const int smemBytes = 4 * GBUF;                 // 73728 (>= 67584 for sT)
    cudaFuncSetAttribute(k_gemm, cudaFuncAttributeMaxDynamicSharedMemorySize, smemBytes);

    k_simi<<<dim3(N_NODES / 128, E_EDGES / 64), 256>>>(x, y, hp);
    k_select<<<E_EDGES, 256>>>();
    k_pack_dv<<<256, 256>>>();
    k_gemm<<<2080, 256, smemBytes>>>(out);
    k_fix<<<128, 256>>>(out);

    size_t gElems = (size_t)N_NODES * N_NODES;
    if ((size_t)out_size >= gElems + (size_t)N_NODES * ZD) {
        cudaMemcpyAsync(out + gElems, x, (size_t)N_NODES * ZD * sizeof(float),
                        cudaMemcpyDeviceToDevice);
    }
}

// round 9
// speedup vs baseline: 12.4188x; 1.5724x over previous
#include <cuda_runtime.h>
#include <cuda_bf16.h>
#include <cstdint>

#define E_EDGES 1024
#define N_NODES 8192
#define ZD      256
#define KK_RANK 819
#define DE_NOM  818
#define W0      (1.0f/818.0f)

// ---- scratch ----
__device__ float    g_simi[(size_t)E_EDGES * N_NODES];  // 32 MB [e][n]
__device__ unsigned g_Hbt[256 * E_EDGES];                // bitmask [n/32][e]
__device__ unsigned g_Hn[(size_t)N_NODES * 32];          // node-major edge bits [n][32]
__device__ float    g_DV2[N_NODES];
__device__ int      g_nDev;
__device__ int      g_devE[E_EDGES];
__device__ int      g_devDE[E_EDGES];

// =====================================================================
// Kernel 1: simi = hyper_clss @ x^T  (fp32 SIMT GEMM)
// =====================================================================
__global__ __launch_bounds__(256) void k_simi(
    const float* __restrict__ x, const int* __restrict__ y,
    const float* __restrict__ hp)
{
    if (blockIdx.x == 0 && blockIdx.y == 0 && threadIdx.x == 0) g_nDev = 0;

    __shared__ float As[32][65];
    __shared__ float Bs[32][129];
    const int be = blockIdx.y * 64, bn = blockIdx.x * 128;
    const int tid = threadIdx.x;
    const int ty = tid >> 4, tx = tid & 15;

    float acc[4][8];
    #pragma unroll
    for (int i = 0; i < 4; i++)
        #pragma unroll
        for (int j = 0; j < 8; j++) acc[i][j] = 0.f;

    for (int k0 = 0; k0 < ZD; k0 += 32) {
        #pragma unroll
        for (int p = 0; p < 2; p++) {
            int idx = tid + p * 256;
            int e = idx >> 3, k4 = (idx & 7) << 2;
            int ge = be + e;
            int row = y[ge >> 4] * 16 + (ge & 15);
            float4 v = *(const float4*)(hp + (size_t)row * ZD + k0 + k4);
            As[k4+0][e] = v.x; As[k4+1][e] = v.y; As[k4+2][e] = v.z; As[k4+3][e] = v.w;
        }
        #pragma unroll
        for (int p = 0; p < 4; p++) {
            int idx = tid + p * 256;
            int n = idx >> 3, k4 = (idx & 7) << 2;
            float4 v = *(const float4*)(x + (size_t)(bn + n) * ZD + k0 + k4);
            Bs[k4+0][n] = v.x; Bs[k4+1][n] = v.y; Bs[k4+2][n] = v.z; Bs[k4+3][n] = v.w;
        }
        __syncthreads();
        #pragma unroll
        for (int k = 0; k < 32; k++) {
            float a[4], b[8];
            #pragma unroll
            for (int mi = 0; mi < 4; mi++) a[mi] = As[k][ty + 16 * mi];
            #pragma unroll
            for (int ni = 0; ni < 8; ni++) b[ni] = Bs[k][tx + 16 * ni];
            #pragma unroll
            for (int mi = 0; mi < 4; mi++)
                #pragma unroll
                for (int ni = 0; ni < 8; ni++)
                    acc[mi][ni] = fmaf(a[mi], b[ni], acc[mi][ni]);
        }
        __syncthreads();
    }
    #pragma unroll
    for (int mi = 0; mi < 4; mi++)
        #pragma unroll
        for (int ni = 0; ni < 8; ni++)
            g_simi[(size_t)(be + ty + 16 * mi) * N_NODES + bn + tx + 16 * ni] = acc[mi][ni];
}

// =====================================================================
// Kernel 2: exact radix select (parallel suffix-scan per level)
// =====================================================================
__global__ __launch_bounds__(256) void k_select()
{
    __shared__ unsigned su[N_NODES];
    __shared__ unsigned hist[256];
    __shared__ unsigned sfx[256];
    __shared__ unsigned s_bin, s_r, s_above;

    const int e = blockIdx.x;
    const int t = threadIdx.x;
    const float* row = g_simi + (size_t)e * N_NODES;

    #pragma unroll 4
    for (int i = 0; i < 32; i++) {
        unsigned b = __float_as_uint(row[i * 256 + t]);
        su[i * 256 + t] = (b & 0x80000000u) ? ~b : (b | 0x80000000u);
    }
    if (t == 0) { s_r = KK_RANK; s_above = 0; }
    __syncthreads();

    unsigned prefix = 0, pmask = 0;
    for (int level = 0; level < 4; level++) {
        int shift = 24 - 8 * level;
        hist[t] = 0;
        __syncthreads();
        #pragma unroll 4
        for (int i = 0; i < 32; i++) {
            unsigned u = su[i * 256 + t];
            if ((u & pmask) == prefix) atomicAdd(&hist[(u >> shift) & 0xFFu], 1u);
        }
        __syncthreads();
        sfx[t] = hist[t];
        __syncthreads();
        #pragma unroll
        for (int off = 1; off < 256; off <<= 1) {
            unsigned v = sfx[t] + ((t + off < 256) ? sfx[t + off] : 0u);
            __syncthreads();
            sfx[t] = v;
            __syncthreads();
        }
        unsigned r = s_r;
        unsigned nxt = (t < 255) ? sfx[t + 1] : 0u;
        if (sfx[t] >= r && nxt < r) {
            s_bin = (unsigned)t;
            s_r = r - nxt;
            s_above += nxt;
        }
        __syncthreads();
        prefix |= (s_bin << shift);
        pmask  |= (0xFFu << shift);
        __syncthreads();
    }

    const unsigned thr = prefix;
    const unsigned de  = s_above;

    unsigned v = 0;
    #pragma unroll
    for (int b = 0; b < 32; b++)
        v |= (su[32 * t + b] > thr) ? (1u << b) : 0u;
    g_Hbt[t * E_EDGES + e] = v;

    if (t == 0 && de != DE_NOM) {
        int idx = atomicAdd(&g_nDev, 1);
        g_devE[idx] = e; g_devDE[idx] = (int)de;
    }
}

// =====================================================================
// Kernel 3: bit transpose -> node-major edge masks g_Hn[n][32] + DV2.
// =====================================================================
__global__ __launch_bounds__(256) void k_pack_dv()
{
    const int w = blockIdx.x;           // node word 0..255
    const int t = threadIdx.x;
    const int warp = t >> 5, lane = t & 31;
    __shared__ int s_cnt[32];
    if (t < 32) s_cnt[t] = 0;
    __syncthreads();

    int myCnt = 0;
    #pragma unroll
    for (int i = 0; i < 4; i++) {
        int ew = warp + 8 * i;          // edge word 0..31
        unsigned v = g_Hbt[w * E_EDGES + ew * 32 + lane];  // edge e = ew*32+lane
        #pragma unroll
        for (int b = 0; b < 32; b++) {
            unsigned word = __ballot_sync(0xFFFFFFFFu, (v >> b) & 1u);
            if (lane == b) {
                g_Hn[(size_t)(w * 32 + b) * 32 + ew] = word;
                myCnt += __popc(word);
            }
        }
    }
    atomicAdd(&s_cnt[lane], myCnt);
    __syncthreads();
    if (t < 32) g_DV2[w * 32 + t] = rsqrtf((float)s_cnt[t]);
}

// =====================================================================
// Kernel 4: O = H^T H via popcount (exact); G = W0*DV2i*DV2j*O
// 128x128 tiles, triangular grid; tiles loaded to smem once.
// =====================================================================
#define TSTR 132    // multiple of 4 -> float4-aligned transposed rows

__global__ __launch_bounds__(256, 2) void k_gemm(float* __restrict__ G)
{
    // triangular decode: block b -> (bi, bj), bj >= bi
    int b = blockIdx.x;
    int bi = (int)(64.5f - sqrtf(64.5f * 64.5f - 2.0f * (float)b));
    while (64 * bi - bi * (bi - 1) / 2 > b) bi--;
    while (64 * (bi + 1) - (bi + 1) * bi / 2 <= b) bi++;
    const int bj = bi + (b - (64 * bi - bi * (bi - 1) / 2));

    extern __shared__ char dynsm[];
    unsigned* sA = (unsigned*)dynsm;            // [32][128] words, 16 KB
    unsigned* sB = sA + 32 * 128;               // 16 KB
    float*    sT = (float*)dynsm;               // [128][TSTR] floats (reuse)

    const int i0 = bi * 128, j0 = bj * 128;
    const int tid = threadIdx.x;
    const int tx = tid & 15, ty = tid >> 4;

    // load both tiles: thread -> row (tid&127), half (tid>>7)
    {
        int r = tid & 127, part = tid >> 7;     // 16 words each
        const uint4* srcA = (const uint4*)(g_Hn + (size_t)(i0 + r) * 32 + part * 16);
        const uint4* srcB = (const uint4*)(g_Hn + (size_t)(j0 + r) * 32 + part * 16);
        #pragma unroll
        for (int jv = 0; jv < 4; jv++) {
            uint4 va = srcA[jv], vb = srcB[jv];
            int e0 = part * 16 + 4 * jv;
            sA[(e0+0)*128 + r] = va.x; sA[(e0+1)*128 + r] = va.y;
            sA[(e0+2)*128 + r] = va.z; sA[(e0+3)*128 + r] = va.w;
            sB[(e0+0)*128 + r] = vb.x; sB[(e0+1)*128 + r] = vb.y;
            sB[(e0+2)*128 + r] = vb.z; sB[(e0+3)*128 + r] = vb.w;
        }
    }
    __syncthreads();

    int acc[8][8];
    #pragma unroll
    for (int a = 0; a < 8; a++)
        #pragma unroll
        for (int c = 0; c < 8; c++) acc[a][c] = 0;

    #pragma unroll 2
    for (int ew = 0; ew < 32; ew++) {
        unsigned a[8], bb[8];
        #pragma unroll
        for (int jm = 0; jm < 8; jm++) a[jm] = sA[ew * 128 + ty + 16 * jm];
        #pragma unroll
        for (int jn = 0; jn < 8; jn++) bb[jn] = sB[ew * 128 + tx + 16 * jn];
        #pragma unroll
        for (int jm = 0; jm < 8; jm++)
            #pragma unroll
            for (int jn = 0; jn < 8; jn++)
                acc[jm][jn] += __popc(a[jm] & bb[jn]);
    }
    __syncthreads();

    // ---- epilogue: scale, store block, mirror via smem transpose ----
    const bool offd = (bi != bj);
    #pragma unroll
    for (int jm = 0; jm < 8; jm++) {
        int rl = ty + 16 * jm;
        float si = g_DV2[i0 + rl] * W0;
        #pragma unroll
        for (int jn = 0; jn < 8; jn++) {
            int cl = tx + 16 * jn;
            float v = (float)acc[jm][jn] * si * g_DV2[j0 + cl];
            G[(size_t)(i0 + rl) * N_NODES + j0 + cl] = v;
            if (offd) sT[cl * TSTR + rl] = v;
        }
    }
    if (offd) {
        __syncthreads();
        #pragma unroll
        for (int t2 = tid; t2 < 4096; t2 += 256) {
            int jr = t2 >> 5, ic = (t2 & 31) << 2;
            float4 v = *(const float4*)&sT[jr * TSTR + ic];
            *(float4*)&G[(size_t)(j0 + jr) * N_NODES + i0 + ic] = v;
        }
    }
}

// =====================================================================
// Kernel 5: exact correction for deviant edges (de != 818); usually no-op
// =====================================================================
__global__ __launch_bounds__(256) void k_fix(float* __restrict__ G)
{
    const int d = blockIdx.x;
    if (d >= g_nDev) return;
    const int e = g_devE[d];
    const int de = g_devDE[d];
    const float delta = 1.0f / (float)de - W0;

    __shared__ int mem[2048];
    __shared__ int cnt;
    if (threadIdx.x == 0) cnt = 0;
    __syncthreads();
    for (int n = threadIdx.x; n < N_NODES; n += 256)
        if ((g_Hn[(size_t)n * 32 + (e >> 5)] >> (e & 31)) & 1u) {
            int p = atomicAdd(&cnt, 1); mem[p] = n;
        }
    __syncthreads();
    const int m = cnt;
    for (int idx = threadIdx.x; idx < m * m; idx += 256) {
        int i = mem[idx / m], j = mem[idx % m];
        atomicAdd(&G[(size_t)i * N_NODES + j], delta * g_DV2[i] * g_DV2[j]);
    }
}

// =====================================================================
extern "C" void kernel_launch(void* const* d_in, const int* in_sizes, int n_in,
                              void* d_out, int out_size)
{
    const float* x  = (const float*)d_in[0];
    const int*   y  = (const int*)d_in[1];
    const float* hp = (const float*)d_in[2];
    float* out = (float*)d_out;

    const int smemBytes = 128 * TSTR * (int)sizeof(float);  // 67584 >= 32KB tiles
    cudaFuncSetAttribute(k_gemm, cudaFuncAttributeMaxDynamicSharedMemorySize, smemBytes);

    k_simi<<<dim3(N_NODES / 128, E_EDGES / 64), 256>>>(x, y, hp);
    k_select<<<E_EDGES, 256>>>();
    k_pack_dv<<<256, 256>>>();
    k_gemm<<<2080, 256, smemBytes>>>(out);
    k_fix<<<128, 256>>>(out);

    size_t gElems = (size_t)N_NODES * N_NODES;
    if ((size_t)out_size >= gElems + (size_t)N_NODES * ZD) {
        cudaMemcpyAsync(out + gElems, x, (size_t)N_NODES * ZD * sizeof(float),
                        cudaMemcpyDeviceToDevice);
    }
}

// round 10
// speedup vs baseline: 12.7087x; 1.0233x over previous
#include <cuda_runtime.h>
#include <cuda_bf16.h>
#include <cstdint>

#define E_EDGES 1024
#define N_NODES 8192
#define ZD      256
#define KK_RANK 819
#define DE_NOM  818
#define W0      (1.0f/818.0f)

// ---- scratch ----
__device__ float    g_simi[(size_t)E_EDGES * N_NODES];  // 32 MB [e][n]
__device__ unsigned g_Hbt[256 * E_EDGES];                // bitmask [n/32][e]
__device__ unsigned g_Hn[(size_t)N_NODES * 32];          // node-major edge bits [n][32]
__device__ float    g_DV2[N_NODES];
__device__ int      g_nDev;
__device__ int      g_devE[E_EDGES];
__device__ int      g_devDE[E_EDGES];

// packed fp32x2 FMA (Blackwell): d = a*b + d per 32-bit lane, exact fp32
__device__ __forceinline__ void ffma2(unsigned long long &d,
                                      unsigned long long a, unsigned long long b)
{
    asm volatile("fma.rn.f32x2 %0, %1, %2, %0;" : "+l"(d) : "l"(a), "l"(b));
}
__device__ __forceinline__ unsigned long long pack2(float v)
{
    unsigned long long r;
    asm("mov.b64 %0, {%1, %1};" : "=l"(r) : "f"(v));
    return r;
}

// =====================================================================
// Kernel 1: simi = hyper_clss @ x^T  (fp32, f32x2-packed FMA)
// Block 64(e) x 128(n); thread (ty,tx) -> rows ty+16mi, col-pairs 2tx+32nj
// =====================================================================
__global__ __launch_bounds__(256) void k_simi(
    const float* __restrict__ x, const int* __restrict__ y,
    const float* __restrict__ hp)
{
    if (blockIdx.x == 0 && blockIdx.y == 0 && threadIdx.x == 0) g_nDev = 0;

    __shared__ float As[32][65];
    __shared__ float Bs[32][130];   // even stride -> aligned LDS.64 pairs
    const int be = blockIdx.y * 64, bn = blockIdx.x * 128;
    const int tid = threadIdx.x;
    const int ty = tid >> 4, tx = tid & 15;

    unsigned long long acc2[4][4];
    #pragma unroll
    for (int i = 0; i < 4; i++)
        #pragma unroll
        for (int j = 0; j < 4; j++) acc2[i][j] = 0ull;

    for (int k0 = 0; k0 < ZD; k0 += 32) {
        #pragma unroll
        for (int p = 0; p < 2; p++) {
            int idx = tid + p * 256;
            int e = idx >> 3, k4 = (idx & 7) << 2;
            int ge = be + e;
            int row = y[ge >> 4] * 16 + (ge & 15);
            float4 v = *(const float4*)(hp + (size_t)row * ZD + k0 + k4);
            As[k4+0][e] = v.x; As[k4+1][e] = v.y; As[k4+2][e] = v.z; As[k4+3][e] = v.w;
        }
        #pragma unroll
        for (int p = 0; p < 4; p++) {
            int idx = tid + p * 256;
            int n = idx >> 3, k4 = (idx & 7) << 2;
            float4 v = *(const float4*)(x + (size_t)(bn + n) * ZD + k0 + k4);
            Bs[k4+0][n] = v.x; Bs[k4+1][n] = v.y; Bs[k4+2][n] = v.z; Bs[k4+3][n] = v.w;
        }
        __syncthreads();
        #pragma unroll
        for (int k = 0; k < 32; k++) {
            unsigned long long ad[4], bd[4];
            #pragma unroll
            for (int mi = 0; mi < 4; mi++) ad[mi] = pack2(As[k][ty + 16 * mi]);
            #pragma unroll
            for (int nj = 0; nj < 4; nj++)
                bd[nj] = *(const unsigned long long*)&Bs[k][2 * tx + 32 * nj];
            #pragma unroll
            for (int mi = 0; mi < 4; mi++)
                #pragma unroll
                for (int nj = 0; nj < 4; nj++)
                    ffma2(acc2[mi][nj], ad[mi], bd[nj]);
        }
        __syncthreads();
    }
    #pragma unroll
    for (int mi = 0; mi < 4; mi++)
        #pragma unroll
        for (int nj = 0; nj < 4; nj++) {
            unsigned lo = (unsigned)(acc2[mi][nj] & 0xFFFFFFFFull);
            unsigned hi = (unsigned)(acc2[mi][nj] >> 32);
            float2 v = make_float2(__uint_as_float(lo), __uint_as_float(hi));
            *(float2*)&g_simi[(size_t)(be + ty + 16 * mi) * N_NODES + bn + 2 * tx + 32 * nj] = v;
        }
}

// =====================================================================
// Kernel 2: exact radix select (parallel suffix-scan per level)
// =====================================================================
__global__ __launch_bounds__(256) void k_select()
{
    __shared__ unsigned su[N_NODES];
    __shared__ unsigned hist[256];
    __shared__ unsigned sfx[256];
    __shared__ unsigned s_bin, s_r, s_above;

    const int e = blockIdx.x;
    const int t = threadIdx.x;
    const float* row = g_simi + (size_t)e * N_NODES;

    #pragma unroll 4
    for (int i = 0; i < 32; i++) {
        unsigned b = __float_as_uint(row[i * 256 + t]);
        su[i * 256 + t] = (b & 0x80000000u) ? ~b : (b | 0x80000000u);
    }
    if (t == 0) { s_r = KK_RANK; s_above = 0; }
    __syncthreads();

    unsigned prefix = 0, pmask = 0;
    for (int level = 0; level < 4; level++) {
        int shift = 24 - 8 * level;
        hist[t] = 0;
        __syncthreads();
        #pragma unroll 4
        for (int i = 0; i < 32; i++) {
            unsigned u = su[i * 256 + t];
            if ((u & pmask) == prefix) atomicAdd(&hist[(u >> shift) & 0xFFu], 1u);
        }
        __syncthreads();
        sfx[t] = hist[t];
        __syncthreads();
        #pragma unroll
        for (int off = 1; off < 256; off <<= 1) {
            unsigned v = sfx[t] + ((t + off < 256) ? sfx[t + off] : 0u);
            __syncthreads();
            sfx[t] = v;
            __syncthreads();
        }
        unsigned r = s_r;
        unsigned nxt = (t < 255) ? sfx[t + 1] : 0u;
        if (sfx[t] >= r && nxt < r) {
            s_bin = (unsigned)t;
            s_r = r - nxt;
            s_above += nxt;
        }
        __syncthreads();
        prefix |= (s_bin << shift);
        pmask  |= (0xFFu << shift);
        __syncthreads();
    }

    const unsigned thr = prefix;
    const unsigned de  = s_above;

    unsigned v = 0;
    #pragma unroll
    for (int b = 0; b < 32; b++)
        v |= (su[32 * t + b] > thr) ? (1u << b) : 0u;
    g_Hbt[t * E_EDGES + e] = v;

    if (t == 0 && de != DE_NOM) {
        int idx = atomicAdd(&g_nDev, 1);
        g_devE[idx] = e; g_devDE[idx] = (int)de;
    }
}

// =====================================================================
// Kernel 3: bit transpose -> node-major edge masks g_Hn[n][32] + DV2.
// =====================================================================
__global__ __launch_bounds__(256) void k_pack_dv()
{
    const int w = blockIdx.x;           // node word 0..255
    const int t = threadIdx.x;
    const int warp = t >> 5, lane = t & 31;
    __shared__ int s_cnt[32];
    if (t < 32) s_cnt[t] = 0;
    __syncthreads();

    int myCnt = 0;
    #pragma unroll
    for (int i = 0; i < 4; i++) {
        int ew = warp + 8 * i;          // edge word 0..31
        unsigned v = g_Hbt[w * E_EDGES + ew * 32 + lane];
        #pragma unroll
        for (int b = 0; b < 32; b++) {
            unsigned word = __ballot_sync(0xFFFFFFFFu, (v >> b) & 1u);
            if (lane == b) {
                g_Hn[(size_t)(w * 32 + b) * 32 + ew] = word;
                myCnt += __popc(word);
            }
        }
    }
    atomicAdd(&s_cnt[lane], myCnt);
    __syncthreads();
    if (t < 32) g_DV2[w * 32 + t] = rsqrtf((float)s_cnt[t]);
}

// =====================================================================
// Kernel 4: O = H^T H via popcount (exact); G = W0*DV2i*DV2j*O
// 128x128 tiles; software-pipelined operand double-buffering.
// =====================================================================
#define TSTR 132

__global__ __launch_bounds__(256, 2) void k_gemm(float* __restrict__ G)
{
    int b = blockIdx.x;
    int bi = (int)(64.5f - sqrtf(64.5f * 64.5f - 2.0f * (float)b));
    while (64 * bi - bi * (bi - 1) / 2 > b) bi--;
    while (64 * (bi + 1) - (bi + 1) * bi / 2 <= b) bi++;
    const int bj = bi + (b - (64 * bi - bi * (bi - 1) / 2));

    extern __shared__ char dynsm[];
    unsigned* sA = (unsigned*)dynsm;            // [32][128] words
    unsigned* sB = sA + 32 * 128;
    float*    sT = (float*)dynsm;               // [128][TSTR] floats (reuse)

    const int i0 = bi * 128, j0 = bj * 128;
    const int tid = threadIdx.x;
    const int tx = tid & 15, ty = tid >> 4;

    {
        int r = tid & 127, part = tid >> 7;
        const uint4* srcA = (const uint4*)(g_Hn + (size_t)(i0 + r) * 32 + part * 16);
        const uint4* srcB = (const uint4*)(g_Hn + (size_t)(j0 + r) * 32 + part * 16);
        #pragma unroll
        for (int jv = 0; jv < 4; jv++) {
            uint4 va = srcA[jv], vb = srcB[jv];
            int e0 = part * 16 + 4 * jv;
            sA[(e0+0)*128 + r] = va.x; sA[(e0+1)*128 + r] = va.y;
            sA[(e0+2)*128 + r] = va.z; sA[(e0+3)*128 + r] = va.w;
            sB[(e0+0)*128 + r] = vb.x; sB[(e0+1)*128 + r] = vb.y;
            sB[(e0+2)*128 + r] = vb.z; sB[(e0+3)*128 + r] = vb.w;
        }
    }
    __syncthreads();

    int acc[8][8];
    #pragma unroll
    for (int a = 0; a < 8; a++)
        #pragma unroll
        for (int c = 0; c < 8; c++) acc[a][c] = 0;

    unsigned a0[8], b0[8], a1[8], b1[8];
    #pragma unroll
    for (int jm = 0; jm < 8; jm++) a0[jm] = sA[ty + 16 * jm];
    #pragma unroll
    for (int jn = 0; jn < 8; jn++) b0[jn] = sB[tx + 16 * jn];

    #pragma unroll
    for (int ew = 0; ew < 32; ew += 2) {
        // prefetch ew+1 while computing ew
        #pragma unroll
        for (int jm = 0; jm < 8; jm++) a1[jm] = sA[(ew + 1) * 128 + ty + 16 * jm];
        #pragma unroll
        for (int jn = 0; jn < 8; jn++) b1[jn] = sB[(ew + 1) * 128 + tx + 16 * jn];
        #pragma unroll
        for (int jm = 0; jm < 8; jm++)
            #pragma unroll
            for (int jn = 0; jn < 8; jn++)
                acc[jm][jn] += __popc(a0[jm] & b0[jn]);
        // prefetch ew+2 while computing ew+1
        if (ew + 2 < 32) {
            #pragma unroll
            for (int jm = 0; jm < 8; jm++) a0[jm] = sA[(ew + 2) * 128 + ty + 16 * jm];
            #pragma unroll
            for (int jn = 0; jn < 8; jn++) b0[jn] = sB[(ew + 2) * 128 + tx + 16 * jn];
        }
        #pragma unroll
        for (int jm = 0; jm < 8; jm++)
            #pragma unroll
            for (int jn = 0; jn < 8; jn++)
                acc[jm][jn] += __popc(a1[jm] & b1[jn]);
    }
    __syncthreads();

    const bool offd = (bi != bj);
    #pragma unroll
    for (int jm = 0; jm < 8; jm++) {
        int rl = ty + 16 * jm;
        float si = g_DV2[i0 + rl] * W0;
        #pragma unroll
        for (int jn = 0; jn < 8; jn++) {
            int cl = tx + 16 * jn;
            float v = (float)acc[jm][jn] * si * g_DV2[j0 + cl];
            G[(size_t)(i0 + rl) * N_NODES + j0 + cl] = v;
            if (offd) sT[cl * TSTR + rl] = v;
        }
    }
    if (offd) {
        __syncthreads();
        #pragma unroll
        for (int t2 = tid; t2 < 4096; t2 += 256) {
            int jr = t2 >> 5, ic = (t2 & 31) << 2;
            float4 v = *(const float4*)&sT[jr * TSTR + ic];
            *(float4*)&G[(size_t)(j0 + jr) * N_NODES + i0 + ic] = v;
        }
    }
}

// =====================================================================
// Kernel 5: exact correction for deviant edges (de != 818); usually no-op
// =====================================================================
__global__ __launch_bounds__(256) void k_fix(float* __restrict__ G)
{
    const int d = blockIdx.x;
    if (d >= g_nDev) return;
    const int e = g_devE[d];
    const int de = g_devDE[d];
    const float delta = 1.0f / (float)de - W0;

    __shared__ int mem[2048];
    __shared__ int cnt;
    if (threadIdx.x == 0) cnt = 0;
    __syncthreads();
    for (int n = threadIdx.x; n < N_NODES; n += 256)
        if ((g_Hn[(size_t)n * 32 + (e >> 5)] >> (e & 31)) & 1u) {
            int p = atomicAdd(&cnt, 1); mem[p] = n;
        }
    __syncthreads();
    const int m = cnt;
    for (int idx = threadIdx.x; idx < m * m; idx += 256) {
        int i = mem[idx / m], j = mem[idx % m];
        atomicAdd(&G[(size_t)i * N_NODES + j], delta * g_DV2[i] * g_DV2[j]);
    }
}

// =====================================================================
extern "C" void kernel_launch(void* const* d_in, const int* in_sizes, int n_in,
                              void* d_out, int out_size)
{
    const float* x  = (const float*)d_in[0];
    const int*   y  = (const int*)d_in[1];
    const float* hp = (const float*)d_in[2];
    float* out = (float*)d_out;

    const int smemBytes = 128 * TSTR * (int)sizeof(float);
    cudaFuncSetAttribute(k_gemm, cudaFuncAttributeMaxDynamicSharedMemorySize, smemBytes);

    k_simi<<<dim3(N_NODES / 128, E_EDGES / 64), 256>>>(x, y, hp);
    k_select<<<E_EDGES, 256>>>();
    k_pack_dv<<<256, 256>>>();
    k_gemm<<<2080, 256, smemBytes>>>(out);
    k_fix<<<128, 256>>>(out);

    size_t gElems = (size_t)N_NODES * N_NODES;
    if ((size_t)out_size >= gElems + (size_t)N_NODES * ZD) {
        cudaMemcpyAsync(out + gElems, x, (size_t)N_NODES * ZD * sizeof(float),
                        cudaMemcpyDeviceToDevice);
    }
}

// round 12
// speedup vs baseline: 14.0447x; 1.1051x over previous
#include <cuda_runtime.h>
#include <cuda_bf16.h>
#include <cstdint>

#define E_EDGES 1024
#define N_NODES 8192
#define ZD      256
#define KK_RANK 819
#define DE_NOM  818
#define W0      (1.0f/818.0f)

// ---- scratch ----
__device__ float    g_simi[(size_t)E_EDGES * N_NODES];  // 32 MB [e][n]
__device__ unsigned g_Hbt[256 * E_EDGES];                // bitmask [n/32][e]
__device__ unsigned g_Hn[(size_t)N_NODES * 32];          // node-major edge bits [n][32]
__device__ float    g_DV2[N_NODES];
__device__ int      g_nDev;
__device__ int      g_devE[E_EDGES];
__device__ int      g_devDE[E_EDGES];

// packed fp32x2 FMA (Blackwell)
__device__ __forceinline__ void ffma2(unsigned long long &d,
                                      unsigned long long a, unsigned long long b)
{
    asm volatile("fma.rn.f32x2 %0, %1, %2, %0;" : "+l"(d) : "l"(a), "l"(b));
}
__device__ __forceinline__ unsigned long long pack2(float v)
{
    unsigned long long r;
    asm("mov.b64 %0, {%1, %1};" : "=l"(r) : "f"(v));
    return r;
}
__device__ __forceinline__ unsigned lop3_xor3(unsigned a, unsigned b, unsigned c)
{
    unsigned d;
    asm("lop3.b32 %0, %1, %2, %3, 0x96;" : "=r"(d) : "r"(a), "r"(b), "r"(c));
    return d;
}
__device__ __forceinline__ unsigned lop3_maj(unsigned a, unsigned b, unsigned c)
{
    unsigned d;
    asm("lop3.b32 %0, %1, %2, %3, 0xE8;" : "=r"(d) : "r"(a), "r"(b), "r"(c));
    return d;
}

// =====================================================================
// Kernel 1: simi = hyper_clss @ x^T  (fp32, f32x2-packed FMA)
// =====================================================================
__global__ __launch_bounds__(256) void k_simi(
    const float* __restrict__ x, const int* __restrict__ y,
    const float* __restrict__ hp)
{
    if (blockIdx.x == 0 && blockIdx.y == 0 && threadIdx.x == 0) g_nDev = 0;

    __shared__ float As[32][65];
    __shared__ float Bs[32][130];
    const int be = blockIdx.y * 64, bn = blockIdx.x * 128;
    const int tid = threadIdx.x;
    const int ty = tid >> 4, tx = tid & 15;

    unsigned long long acc2[4][4];
    #pragma unroll
    for (int i = 0; i < 4; i++)
        #pragma unroll
        for (int j = 0; j < 4; j++) acc2[i][j] = 0ull;

    for (int k0 = 0; k0 < ZD; k0 += 32) {
        #pragma unroll
        for (int p = 0; p < 2; p++) {
            int idx = tid + p * 256;
            int e = idx >> 3, k4 = (idx & 7) << 2;
            int ge = be + e;
            int row = y[ge >> 4] * 16 + (ge & 15);
            float4 v = *(const float4*)(hp + (size_t)row * ZD + k0 + k4);
            As[k4+0][e] = v.x; As[k4+1][e] = v.y; As[k4+2][e] = v.z; As[k4+3][e] = v.w;
        }
        #pragma unroll
        for (int p = 0; p < 4; p++) {
            int idx = tid + p * 256;
            int n = idx >> 3, k4 = (idx & 7) << 2;
            float4 v = *(const float4*)(x + (size_t)(bn + n) * ZD + k0 + k4);
            Bs[k4+0][n] = v.x; Bs[k4+1][n] = v.y; Bs[k4+2][n] = v.z; Bs[k4+3][n] = v.w;
        }
        __syncthreads();
        #pragma unroll
        for (int k = 0; k < 32; k++) {
            unsigned long long ad[4], bd[4];
            #pragma unroll
            for (int mi = 0; mi < 4; mi++) ad[mi] = pack2(As[k][ty + 16 * mi]);
            #pragma unroll
            for (int nj = 0; nj < 4; nj++)
                bd[nj] = *(const unsigned long long*)&Bs[k][2 * tx + 32 * nj];
            #pragma unroll
            for (int mi = 0; mi < 4; mi++)
                #pragma unroll
                for (int nj = 0; nj < 4; nj++)
                    ffma2(acc2[mi][nj], ad[mi], bd[nj]);
        }
        __syncthreads();
    }
    #pragma unroll
    for (int mi = 0; mi < 4; mi++)
        #pragma unroll
        for (int nj = 0; nj < 4; nj++) {
            unsigned lo = (unsigned)(acc2[mi][nj] & 0xFFFFFFFFull);
            unsigned hi = (unsigned)(acc2[mi][nj] >> 32);
            float2 v = make_float2(__uint_as_float(lo), __uint_as_float(hi));
            *(float2*)&g_simi[(size_t)(be + ty + 16 * mi) * N_NODES + bn + 2 * tx + 32 * nj] = v;
        }
}

// =====================================================================
// Kernel 2: exact radix select (suffix-scan; race-free winner update:
// all threads snapshot s_r, BARRIER, then the unique winner writes)
// =====================================================================
__global__ __launch_bounds__(256) void k_select()
{
    __shared__ unsigned su[N_NODES];
    __shared__ unsigned hist[256];
    __shared__ unsigned sfx[256];
    __shared__ unsigned s_bin, s_r, s_above;

    const int e = blockIdx.x;
    const int t = threadIdx.x;
    const float* row = g_simi + (size_t)e * N_NODES;

    #pragma unroll 4
    for (int i = 0; i < 32; i++) {
        unsigned b = __float_as_uint(row[i * 256 + t]);
        su[i * 256 + t] = (b & 0x80000000u) ? ~b : (b | 0x80000000u);
    }
    if (t == 0) { s_r = KK_RANK; s_above = 0; }
    __syncthreads();

    unsigned prefix = 0, pmask = 0;
    for (int level = 0; level < 4; level++) {
        int shift = 24 - 8 * level;
        hist[t] = 0;
        __syncthreads();
        #pragma unroll 4
        for (int i = 0; i < 32; i++) {
            unsigned u = su[i * 256 + t];
            if ((u & pmask) == prefix) atomicAdd(&hist[(u >> shift) & 0xFFu], 1u);
        }
        __syncthreads();
        sfx[t] = hist[t];
        __syncthreads();
        #pragma unroll
        for (int off = 1; off < 256; off <<= 1) {
            unsigned v = sfx[t] + ((t + off < 256) ? sfx[t + off] : 0u);
            __syncthreads();
            sfx[t] = v;
            __syncthreads();
        }
        // snapshot, then barrier, then unique winner writes (no read/write race)
        const unsigned r_cur = s_r;
        const unsigned nxt   = (t < 255) ? sfx[t + 1] : 0u;
        const bool winner    = (sfx[t] >= r_cur) && (nxt < r_cur);
        __syncthreads();
        if (winner) {
            s_bin = (unsigned)t;
            s_r = r_cur - nxt;
            s_above += nxt;
        }
        __syncthreads();
        prefix |= (s_bin << shift);
        pmask  |= (0xFFu << shift);
        __syncthreads();
    }

    const unsigned thr = prefix;
    const unsigned de  = s_above;

    unsigned v = 0;
    #pragma unroll
    for (int b = 0; b < 32; b++)
        v |= (su[32 * t + b] > thr) ? (1u << b) : 0u;
    g_Hbt[t * E_EDGES + e] = v;

    if (t == 0 && de != DE_NOM) {
        int idx = atomicAdd(&g_nDev, 1);
        g_devE[idx] = e; g_devDE[idx] = (int)de;
    }
}

// =====================================================================
// Kernel 3: bit transpose -> node-major edge masks g_Hn[n][32] + DV2.
// =====================================================================
__global__ __launch_bounds__(256) void k_pack_dv()
{
    const int w = blockIdx.x;
    const int t = threadIdx.x;
    const int warp = t >> 5, lane = t & 31;
    __shared__ int s_cnt[32];
    if (t < 32) s_cnt[t] = 0;
    __syncthreads();

    int myCnt = 0;
    #pragma unroll
    for (int i = 0; i < 4; i++) {
        int ew = warp + 8 * i;
        unsigned v = g_Hbt[w * E_EDGES + ew * 32 + lane];
        #pragma unroll
        for (int b = 0; b < 32; b++) {
            unsigned word = __ballot_sync(0xFFFFFFFFu, (v >> b) & 1u);
            if (lane == b) {
                g_Hn[(size_t)(w * 32 + b) * 32 + ew] = word;
                myCnt += __popc(word);
            }
        }
    }
    atomicAdd(&s_cnt[lane], myCnt);
    __syncthreads();
    if (t < 32) g_DV2[w * 32 + t] = rsqrtf((float)s_cnt[t]);
}

// =====================================================================
// Kernel 4: O = H^T H via Harley-Seal CSA popcount (exact)
// 128x128 tiles; 512 threads; 8x4 accs/thread; HS-2 over word pairs.
// =====================================================================
#define TSTR 132

__global__ __launch_bounds__(512, 1) void k_gemm(float* __restrict__ G)
{
    int b = blockIdx.x;
    int bi = (int)(64.5f - sqrtf(64.5f * 64.5f - 2.0f * (float)b));
    while (64 * bi - bi * (bi - 1) / 2 > b) bi--;
    while (64 * (bi + 1) - (bi + 1) * bi / 2 <= b) bi++;
    const int bj = bi + (b - (64 * bi - bi * (bi - 1) / 2));

    extern __shared__ char dynsm[];
    unsigned* sA = (unsigned*)dynsm;            // [32 ew][128 row]
    unsigned* sB = sA + 32 * 128;
    float*    sT = (float*)dynsm;               // [128][TSTR] floats (reuse)

    const int i0 = bi * 128, j0 = bj * 128;
    const int tid = threadIdx.x;
    const int lane = tid & 31;                  // col base
    const int ty = tid >> 5;                    // row base 0..15

    #pragma unroll
    for (int u = 0; u < 2; u++) {
        int idx = tid * 2 + u;                  // 0..1023
        int r = idx >> 3, q = (idx & 7) << 2;
        uint4 va = *(const uint4*)(g_Hn + (size_t)(i0 + r) * 32 + q);
        uint4 vb = *(const uint4*)(g_Hn + (size_t)(j0 + r) * 32 + q);
        sA[(q+0)*128 + r] = va.x; sA[(q+1)*128 + r] = va.y;
        sA[(q+2)*128 + r] = va.z; sA[(q+3)*128 + r] = va.w;
        sB[(q+0)*128 + r] = vb.x; sB[(q+1)*128 + r] = vb.y;
        sB[(q+2)*128 + r] = vb.z; sB[(q+3)*128 + r] = vb.w;
    }
    __syncthreads();

    int acc[8][4];
    unsigned ones[8][4];
    #pragma unroll
    for (int jm = 0; jm < 8; jm++)
        #pragma unroll
        for (int jn = 0; jn < 4; jn++) { acc[jm][jn] = 0; ones[jm][jn] = 0u; }

    #pragma unroll
    for (int ew = 0; ew < 32; ew += 2) {
        unsigned a0[8], a1[8], b0[4], b1[4];
        #pragma unroll
        for (int jm = 0; jm < 8; jm++) {
            a0[jm] = sA[ ew      * 128 + ty + 16 * jm];
            a1[jm] = sA[(ew + 1) * 128 + ty + 16 * jm];
        }
        #pragma unroll
        for (int jn = 0; jn < 4; jn++) {
            b0[jn] = sB[ ew      * 128 + lane + 32 * jn];
            b1[jn] = sB[(ew + 1) * 128 + lane + 32 * jn];
        }
        #pragma unroll
        for (int jm = 0; jm < 8; jm++)
            #pragma unroll
            for (int jn = 0; jn < 4; jn++) {
                unsigned t0 = a0[jm] & b0[jn];
                unsigned t1 = a1[jm] & b1[jn];
                unsigned o  = ones[jm][jn];
                ones[jm][jn] = lop3_xor3(o, t0, t1);
                acc[jm][jn] += __popc(lop3_maj(o, t0, t1));
            }
    }
    #pragma unroll
    for (int jm = 0; jm < 8; jm++)
        #pragma unroll
        for (int jn = 0; jn < 4; jn++)
            acc[jm][jn] = 2 * acc[jm][jn] + __popc(ones[jm][jn]);

    __syncthreads();   // done reading sA/sB before sT reuse

    const bool offd = (bi != bj);
    #pragma unroll
    for (int jm = 0; jm < 8; jm++) {
        int rl = ty + 16 * jm;
        float si = g_DV2[i0 + rl] * W0;
        #pragma unroll
        for (int jn = 0; jn < 4; jn++) {
            int cl = lane + 32 * jn;
            float v = (float)acc[jm][jn] * si * g_DV2[j0 + cl];
            G[(size_t)(i0 + rl) * N_NODES + j0 + cl] = v;
            if (offd) sT[cl * TSTR + rl] = v;
        }
    }
    if (offd) {
        __syncthreads();
        #pragma unroll
        for (int t2 = tid; t2 < 4096; t2 += 512) {
            int jr = t2 >> 5, ic = (t2 & 31) << 2;
            float4 v = *(const float4*)&sT[jr * TSTR + ic];
            *(float4*)&G[(size_t)(j0 + jr) * N_NODES + i0 + ic] = v;
        }
    }
}

// =====================================================================
// Kernel 5: exact correction for deviant edges (de != 818); usually no-op
// =====================================================================
__global__ __launch_bounds__(256) void k_fix(float* __restrict__ G)
{
    const int d = blockIdx.x;
    if (d >= g_nDev) return;
    const int e = g_devE[d];
    const int de = g_devDE[d];
    const float delta = 1.0f / (float)de - W0;

    __shared__ int mem[2048];
    __shared__ int cnt;
    if (threadIdx.x == 0) cnt = 0;
    __syncthreads();
    for (int n = threadIdx.x; n < N_NODES; n += 256)
        if ((g_Hn[(size_t)n * 32 + (e >> 5)] >> (e & 31)) & 1u) {
            int p = atomicAdd(&cnt, 1); mem[p] = n;
        }
    __syncthreads();
    const int m = cnt;
    for (int idx = threadIdx.x; idx < m * m; idx += 256) {
        int i = mem[idx / m], j = mem[idx % m];
        atomicAdd(&G[(size_t)i * N_NODES + j], delta * g_DV2[i] * g_DV2[j]);
    }
}

// =====================================================================
extern "C" void kernel_launch(void* const* d_in, const int* in_sizes, int n_in,
                              void* d_out, int out_size)
{
    const float* x  = (const float*)d_in[0];
    const int*   y  = (const int*)d_in[1];
    const float* hp = (const float*)d_in[2];
    float* out = (float*)d_out;

    const int smemBytes = 128 * TSTR * (int)sizeof(float);
    cudaFuncSetAttribute(k_gemm, cudaFuncAttributeMaxDynamicSharedMemorySize, smemBytes);

    k_simi<<<dim3(N_NODES / 128, E_EDGES / 64), 256>>>(x, y, hp);
    k_select<<<E_EDGES, 256>>>();
    k_pack_dv<<<256, 256>>>();
    k_gemm<<<2080, 512, smemBytes>>>(out);
    k_fix<<<128, 256>>>(out);

    size_t gElems = (size_t)N_NODES * N_NODES;
    if ((size_t)out_size >= gElems + (size_t)N_NODES * ZD) {
        cudaMemcpyAsync(out + gElems, x, (size_t)N_NODES * ZD * sizeof(float),
                        cudaMemcpyDeviceToDevice);
    }
}